// round 4
// baseline (speedup 1.0000x reference)
#include <cuda_runtime.h>

// ---------------- problem constants ----------------
#define T_SEQ 2048
#define NB    2
#define NH    16
#define HS    64
#define CEMB  1024
#define C3    3072

// ---------------- device scratch (allocation-free rule: static globals) ----
__device__ float g_q[NB * NH * T_SEQ * HS];     // [b][h][t][d]
__device__ float g_k[NB * NH * T_SEQ * HS];
__device__ float g_v[NB * NH * T_SEQ * HS];
__device__ float g_att[NB * T_SEQ * CEMB];      // [b][t][h*64+d]

// ============================================================================
// Tiled fp32 GEMM: C[M,N] = A[M,K] @ W[K,N] + bias
// BM=128, BN=64, BK=16, 256 threads, 8x4 per-thread microtile.
// MODE 0: A = x, epilogue scatters into g_q/g_k/g_v  (N = 3072)
// MODE 1: A = g_att, epilogue writes C + bias        (N = 1024)
// ============================================================================
template <int MODE>
__global__ void __launch_bounds__(256)
sgemm_k(const float* __restrict__ Ain, const float* __restrict__ W,
        const float* __restrict__ bias, float* __restrict__ C, int N)
{
    constexpr int BM = 128, BN = 64, BK = 16;
    __shared__ float As[BK][BM + 1];   // stride 129: conflict-light transpose
    __shared__ float Bs[BK][BN];

    const float* A = (MODE == 0) ? Ain : (const float*)g_att;

    const int tid = threadIdx.x;
    const int m0  = blockIdx.y * BM;
    const int n0  = blockIdx.x * BN;
    const int ty  = tid >> 4;          // 0..15  (M direction, 8 rows each)
    const int tx  = tid & 15;          // 0..15  (N direction, 4 cols each)

    const int rowA = tid >> 2;         // 0..63
    const int c4A  = (tid & 3) * 4;    // 0,4,8,12
    const int rowB = tid >> 4;         // 0..15
    const int c4B  = (tid & 15) * 4;   // 0..60

    float acc[8][4];
#pragma unroll
    for (int i = 0; i < 8; i++)
#pragma unroll
        for (int j = 0; j < 4; j++) acc[i][j] = 0.0f;

    for (int kt = 0; kt < CEMB; kt += BK) {
        // load A tile 128x16 (transpose into As[k][m])
#pragma unroll
        for (int p = 0; p < 2; p++) {
            int r = rowA + p * 64;
            float4 t = *(const float4*)(A + (size_t)(m0 + r) * CEMB + kt + c4A);
            As[c4A + 0][r] = t.x;
            As[c4A + 1][r] = t.y;
            As[c4A + 2][r] = t.z;
            As[c4A + 3][r] = t.w;
        }
        // load W tile 16x64
        {
            float4 t = *(const float4*)(W + (size_t)(kt + rowB) * N + n0 + c4B);
            *(float4*)&Bs[rowB][c4B] = t;
        }
        __syncthreads();

#pragma unroll
        for (int kk = 0; kk < BK; kk++) {
            float a[8];
#pragma unroll
            for (int i = 0; i < 8; i++) a[i] = As[kk][ty * 8 + i];
            float4 b4 = *(const float4*)&Bs[kk][tx * 4];
            float bv[4] = {b4.x, b4.y, b4.z, b4.w};
#pragma unroll
            for (int i = 0; i < 8; i++)
#pragma unroll
                for (int j = 0; j < 4; j++)
                    acc[i][j] = fmaf(a[i], bv[j], acc[i][j]);
        }
        __syncthreads();
    }

    if (MODE == 0) {
        // scatter epilogue: n -> (h, which, d); m -> (b, t)
#pragma unroll
        for (int i = 0; i < 8; i++) {
            int m = m0 + ty * 8 + i;
            int b = m >> 11;               // /T_SEQ
            int t = m & (T_SEQ - 1);
#pragma unroll
            for (int j = 0; j < 4; j++) {
                int n = n0 + tx * 4 + j;
                float val = acc[i][j] + bias[n];
                int h = n / 192;
                int e = n - h * 192;
                int which = e >> 6;
                int d = e & 63;
                size_t dst = ((size_t)((b * NH + h) * T_SEQ + t)) * HS + d;
                if (which == 0)      g_q[dst] = val;
                else if (which == 1) g_k[dst] = val;
                else                 g_v[dst] = val;
            }
        }
    } else {
#pragma unroll
        for (int i = 0; i < 8; i++) {
            int m = m0 + ty * 8 + i;
#pragma unroll
            for (int j = 0; j < 4; j++) {
                int n = n0 + tx * 4 + j;
                C[(size_t)m * N + n] = acc[i][j] + bias[n];
            }
        }
    }
}

// ============================================================================
// Causal flash attention, fp32. One CTA per (q-tile of 64, head, batch).
// 256 threads = 16x16; each thread owns a 4x4 microtile for S and for O.
// Online softmax with 16-lane shuffle reductions. P aliases the K smem buffer.
// Dynamic smem: 3 * 64 * 65 * 4 = 49,920 bytes.
// ============================================================================
#define SMS 65   // smem row stride (floats) for 64-wide tiles

__global__ void __launch_bounds__(256)
attn_k(void)
{
    extern __shared__ float sm[];
    float* Qs  = sm;                 // [64][65]
    float* KPs = sm + 64 * SMS;      // K tile, then aliased as P tile
    float* Vs  = sm + 2 * 64 * SMS;  // [64][65]

    const int qt = blockIdx.x;
    const int h  = blockIdx.y;
    const int b  = blockIdx.z;
    const int q0 = qt * 64;

    const size_t base = (size_t)(b * NH + h) * T_SEQ * HS;
    const float* Qg = g_q + base;
    const float* Kg = g_k + base;
    const float* Vg = g_v + base;

    const int tid = threadIdx.x;
    const int tq  = tid >> 4;   // 0..15, 4 query rows each
    const int tk  = tid & 15;   // 0..15, 4 key cols / 4 value dims each

    // ---- load Q tile, pre-scaled by 1/sqrt(hs) = 0.125 ----
#pragma unroll
    for (int i = 0; i < 4; i++) {
        int idx = tid + i * 256;          // float4 index, 1024 total
        int r = idx >> 4;
        int c = (idx & 15) * 4;
        float4 t = *(const float4*)(Qg + (size_t)(q0 + r) * HS + c);
        Qs[r * SMS + c + 0] = t.x * 0.125f;
        Qs[r * SMS + c + 1] = t.y * 0.125f;
        Qs[r * SMS + c + 2] = t.z * 0.125f;
        Qs[r * SMS + c + 3] = t.w * 0.125f;
    }

    float o[4][4];
#pragma unroll
    for (int i = 0; i < 4; i++)
#pragma unroll
        for (int j = 0; j < 4; j++) o[i][j] = 0.0f;
    float mrow[4], lrow[4];
#pragma unroll
    for (int i = 0; i < 4; i++) { mrow[i] = -1e30f; lrow[i] = 0.0f; }

    for (int kt = 0; kt <= qt; kt++) {
        __syncthreads();   // protects Qs (1st iter) and KPs/Vs from prior readers
        // ---- load K, V tiles ----
#pragma unroll
        for (int i = 0; i < 4; i++) {
            int idx = tid + i * 256;
            int r = idx >> 4;
            int c = (idx & 15) * 4;
            float4 tK = *(const float4*)(Kg + (size_t)(kt * 64 + r) * HS + c);
            KPs[r * SMS + c + 0] = tK.x;
            KPs[r * SMS + c + 1] = tK.y;
            KPs[r * SMS + c + 2] = tK.z;
            KPs[r * SMS + c + 3] = tK.w;
            float4 tV = *(const float4*)(Vg + (size_t)(kt * 64 + r) * HS + c);
            Vs[r * SMS + c + 0] = tV.x;
            Vs[r * SMS + c + 1] = tV.y;
            Vs[r * SMS + c + 2] = tV.z;
            Vs[r * SMS + c + 3] = tV.w;
        }
        __syncthreads();

        // ---- S = Q @ K^T  (4x4 per thread) ----
        float s[4][4];
#pragma unroll
        for (int i = 0; i < 4; i++)
#pragma unroll
            for (int j = 0; j < 4; j++) s[i][j] = 0.0f;

#pragma unroll 4
        for (int d = 0; d < HS; d++) {
            float a[4], bb[4];
#pragma unroll
            for (int i = 0; i < 4; i++) a[i]  = Qs [(tq * 4 + i) * SMS + d];
#pragma unroll
            for (int j = 0; j < 4; j++) bb[j] = KPs[(tk * 4 + j) * SMS + d];
#pragma unroll
            for (int i = 0; i < 4; i++)
#pragma unroll
                for (int j = 0; j < 4; j++)
                    s[i][j] = fmaf(a[i], bb[j], s[i][j]);
        }

        // ---- causal mask on diagonal tile ----
        if (kt == qt) {
#pragma unroll
            for (int i = 0; i < 4; i++)
#pragma unroll
                for (int j = 0; j < 4; j++)
                    if (tk * 4 + j > tq * 4 + i) s[i][j] = -1e30f;
        }

        // ---- online softmax (row groups of 16 lanes, aligned in warp) ----
#pragma unroll
        for (int i = 0; i < 4; i++) {
            float mt = fmaxf(fmaxf(s[i][0], s[i][1]), fmaxf(s[i][2], s[i][3]));
#pragma unroll
            for (int off = 1; off < 16; off <<= 1)
                mt = fmaxf(mt, __shfl_xor_sync(0xffffffffu, mt, off));
            float mnew  = fmaxf(mrow[i], mt);
            float scale = __expf(mrow[i] - mnew);
            mrow[i] = mnew;
            float ssum = 0.0f;
#pragma unroll
            for (int j = 0; j < 4; j++) {
                float p = __expf(s[i][j] - mnew);
                s[i][j] = p;
                ssum += p;
            }
#pragma unroll
            for (int off = 1; off < 16; off <<= 1)
                ssum += __shfl_xor_sync(0xffffffffu, ssum, off);
            lrow[i] = lrow[i] * scale + ssum;
#pragma unroll
            for (int j = 0; j < 4; j++) o[i][j] *= scale;
        }

        __syncthreads();   // everyone done reading K before P overwrites it
#pragma unroll
        for (int i = 0; i < 4; i++)
#pragma unroll
            for (int j = 0; j < 4; j++)
                KPs[(tq * 4 + i) * SMS + tk * 4 + j] = s[i][j];
        __syncthreads();

        // ---- O += P @ V  (4 query rows x 4 head dims per thread) ----
#pragma unroll 4
        for (int kk = 0; kk < 64; kk++) {
            float a[4], bb[4];
#pragma unroll
            for (int i = 0; i < 4; i++) a[i]  = KPs[(tq * 4 + i) * SMS + kk];
#pragma unroll
            for (int j = 0; j < 4; j++) bb[j] = Vs [kk * SMS + tk * 4 + j];
#pragma unroll
            for (int i = 0; i < 4; i++)
#pragma unroll
                for (int j = 0; j < 4; j++)
                    o[i][j] = fmaf(a[i], bb[j], o[i][j]);
        }
    }

    // ---- normalize and write to g_att [b][t][h*64+d] ----
#pragma unroll
    for (int i = 0; i < 4; i++) {
        float inv = 1.0f / lrow[i];
        int t = q0 + tq * 4 + i;
        float* dst = g_att + ((size_t)(b * T_SEQ + t)) * CEMB + h * HS + tk * 4;
#pragma unroll
        for (int j = 0; j < 4; j++) dst[j] = o[i][j] * inv;
    }
}

// ============================================================================
// launch
// ============================================================================
extern "C" void kernel_launch(void* const* d_in, const int* in_sizes, int n_in,
                              void* d_out, int out_size)
{
    const float* x    = (const float*)d_in[0];
    const float* Wqkv = (const float*)d_in[1];
    const float* bqkv = (const float*)d_in[2];
    const float* Wo   = (const float*)d_in[3];
    const float* bo   = (const float*)d_in[4];
    float* out = (float*)d_out;

    // attention kernel needs 49,920 B dynamic smem (> 48 KB default cap).
    // cudaFuncSetAttribute is not a stream op -> graph-capture safe.
    cudaFuncSetAttribute(attn_k, cudaFuncAttributeMaxDynamicSharedMemorySize,
                         3 * 64 * SMS * (int)sizeof(float));

    // 1) QKV projection + scatter to g_q/g_k/g_v
    sgemm_k<0><<<dim3(C3 / 64, (NB * T_SEQ) / 128), 256>>>(x, Wqkv, bqkv, nullptr, C3);

    // 2) causal flash attention -> g_att
    attn_k<<<dim3(T_SEQ / 64, NH, NB), 256, 3 * 64 * SMS * (int)sizeof(float)>>>();

    // 3) output projection -> d_out
    sgemm_k<1><<<dim3(CEMB / 64, (NB * T_SEQ) / 128), 256>>>(nullptr, Wo, bo, out, CEMB);
}

// round 5
// speedup vs baseline: 1.1427x; 1.1427x over previous
#include <cuda_runtime.h>

// ---------------- problem constants ----------------
#define T_SEQ 2048
#define NB    2
#define NH    16
#define HS    64
#define CEMB  1024
#define C3    3072

// ---------------- device scratch (allocation-free rule: static globals) ----
__device__ float g_q[NB * NH * T_SEQ * HS];     // [b][h][t][d]
__device__ float g_k[NB * NH * T_SEQ * HS];
__device__ float g_v[NB * NH * T_SEQ * HS];
__device__ float g_att[NB * T_SEQ * CEMB];      // [b][t][h*64+d]

// ============================================================================
// Tiled fp32 GEMM: C[M,N] = A[M,K] @ W[K,N] + bias
// BM=128, BN=128, BK=16, 256 threads, 8x8 microtile, double-buffered smem,
// register prefetch of next global tile (1 __syncthreads per K-tile).
// MODE 0: A = x, epilogue scatters into g_q/g_k/g_v  (N = 3072)
// MODE 1: A = g_att, epilogue writes C + bias        (N = 1024)
// ============================================================================
template <int MODE>
__global__ void __launch_bounds__(256)
sgemm2(const float* __restrict__ Ain, const float* __restrict__ W,
       const float* __restrict__ bias, float* __restrict__ C, int N)
{
    constexpr int BK = 16, AST = 132, BST = 132;
    __shared__ float As[2][BK][AST];   // As[buf][k][m]  (transposed A)
    __shared__ float Bs[2][BK][BST];   // Bs[buf][k][n]

    const float* A = (MODE == 0) ? Ain : (const float*)g_att;

    const int tid = threadIdx.x;
    const int m0  = blockIdx.y * 128;
    const int n0  = blockIdx.x * 128;
    const int ty  = tid >> 4;          // 0..15  (M dir, 8 rows)
    const int tx  = tid & 15;          // 0..15  (N dir, 8 cols)

    const int rA = tid >> 2;           // 0..63
    const int cA = (tid & 3) * 4;      // 0,4,8,12
    const int rB = tid >> 4;           // 0..15
    const int cB = (tid & 15) * 8;     // 0..120

    const float* Ap0 = A + (size_t)(m0 + rA) * CEMB + cA;
    const float* Ap1 = A + (size_t)(m0 + rA + 64) * CEMB + cA;
    const float* Bp  = W + (size_t)rB * N + n0 + cB;

    // prologue: load K-tile 0 into buffer 0
    {
        float4 a0 = *(const float4*)Ap0;
        float4 a1 = *(const float4*)Ap1;
        float4 b0 = *(const float4*)Bp;
        float4 b1 = *(const float4*)(Bp + 4);
        As[0][cA + 0][rA] = a0.x; As[0][cA + 1][rA] = a0.y;
        As[0][cA + 2][rA] = a0.z; As[0][cA + 3][rA] = a0.w;
        As[0][cA + 0][rA + 64] = a1.x; As[0][cA + 1][rA + 64] = a1.y;
        As[0][cA + 2][rA + 64] = a1.z; As[0][cA + 3][rA + 64] = a1.w;
        *(float4*)&Bs[0][rB][cB]     = b0;
        *(float4*)&Bs[0][rB][cB + 4] = b1;
    }
    __syncthreads();

    float acc[8][8];
#pragma unroll
    for (int i = 0; i < 8; i++)
#pragma unroll
        for (int j = 0; j < 8; j++) acc[i][j] = 0.0f;

    constexpr int NK = CEMB / BK;  // 64
    for (int kt = 0; kt < NK; kt++) {
        const int buf = kt & 1;
        float4 a0, a1, b0, b1;
        const bool more = (kt + 1 < NK);
        if (more) {
            const int off = (kt + 1) * BK;
            a0 = *(const float4*)(Ap0 + off);
            a1 = *(const float4*)(Ap1 + off);
            b0 = *(const float4*)(Bp + (size_t)off * N);
            b1 = *(const float4*)(Bp + (size_t)off * N + 4);
        }

#pragma unroll
        for (int kk = 0; kk < BK; kk++) {
            float4 x0 = *(const float4*)&As[buf][kk][ty * 8];
            float4 x1 = *(const float4*)&As[buf][kk][ty * 8 + 4];
            float4 y0 = *(const float4*)&Bs[buf][kk][tx * 8];
            float4 y1 = *(const float4*)&Bs[buf][kk][tx * 8 + 4];
            float a[8]  = {x0.x, x0.y, x0.z, x0.w, x1.x, x1.y, x1.z, x1.w};
            float bb[8] = {y0.x, y0.y, y0.z, y0.w, y1.x, y1.y, y1.z, y1.w};
#pragma unroll
            for (int i = 0; i < 8; i++)
#pragma unroll
                for (int j = 0; j < 8; j++)
                    acc[i][j] = fmaf(a[i], bb[j], acc[i][j]);
        }

        if (more) {
            const int nb = buf ^ 1;
            As[nb][cA + 0][rA] = a0.x; As[nb][cA + 1][rA] = a0.y;
            As[nb][cA + 2][rA] = a0.z; As[nb][cA + 3][rA] = a0.w;
            As[nb][cA + 0][rA + 64] = a1.x; As[nb][cA + 1][rA + 64] = a1.y;
            As[nb][cA + 2][rA + 64] = a1.z; As[nb][cA + 3][rA + 64] = a1.w;
            *(float4*)&Bs[nb][rB][cB]     = b0;
            *(float4*)&Bs[nb][rB][cB + 4] = b1;
        }
        __syncthreads();
    }

    // ---------------- epilogue ----------------
    const int n_base = n0 + tx * 8;
    float bv[8];
#pragma unroll
    for (int j = 0; j < 8; j++) bv[j] = bias[n_base + j];

    if (MODE == 0) {
        // n -> (h, which, d); an 8-wide run never crosses a 64-boundary
        const int hh    = n_base / 192;
        const int e     = n_base - hh * 192;
        const int which = e >> 6;
        const int d     = e & 63;
        float* arr = (which == 0) ? g_q : (which == 1) ? g_k : g_v;
#pragma unroll
        for (int i = 0; i < 8; i++) {
            int m    = m0 + ty * 8 + i;
            int bidx = m >> 11;              // / T_SEQ
            int t    = m & (T_SEQ - 1);
            float* dst = arr + ((size_t)((bidx * NH + hh) * T_SEQ + t)) * HS + d;
            float4 o0 = make_float4(acc[i][0] + bv[0], acc[i][1] + bv[1],
                                    acc[i][2] + bv[2], acc[i][3] + bv[3]);
            float4 o1 = make_float4(acc[i][4] + bv[4], acc[i][5] + bv[5],
                                    acc[i][6] + bv[6], acc[i][7] + bv[7]);
            *(float4*)dst       = o0;
            *(float4*)(dst + 4) = o1;
        }
    } else {
#pragma unroll
        for (int i = 0; i < 8; i++) {
            int m = m0 + ty * 8 + i;
            float* dst = C + (size_t)m * N + n_base;
            float4 o0 = make_float4(acc[i][0] + bv[0], acc[i][1] + bv[1],
                                    acc[i][2] + bv[2], acc[i][3] + bv[3]);
            float4 o1 = make_float4(acc[i][4] + bv[4], acc[i][5] + bv[5],
                                    acc[i][6] + bv[6], acc[i][7] + bv[7]);
            *(float4*)dst       = o0;
            *(float4*)(dst + 4) = o1;
        }
    }
}

// ============================================================================
// Causal flash attention, fp32. BQ = BKV = 128. One CTA per (q-tile, head, b).
// 256 threads = 16x16. S phase: 8x8 microtile, Q and K transposed in smem so
// both operand reads are LDS.128 (1.0 B/FMA). PV phase: 8 rows x 4 dims,
// P-row reads are warp broadcasts. Online softmax, 16-lane shfl reductions.
// Dynamic smem: Qt[64][132] + Kt[64][132] + Vs[128][68] + Ps[128][132]
//             = 169,984 bytes.
// ============================================================================
__global__ void __launch_bounds__(256)
attn2(void)
{
    extern __shared__ float sm[];
    float* Qt = sm;                     // [64][132]   Qt[d][row], pre-scaled
    float* Kt = Qt + 64 * 132;          // [64][132]   Kt[d][col]
    float* Vs = Kt + 64 * 132;          // [128][68]   Vs[kv][dim]
    float* Ps = Vs + 128 * 68;          // [128][132]  Ps[row][col]

    const int qt = gridDim.x - 1 - blockIdx.x;   // heavy tiles first
    const int h  = blockIdx.y;
    const int b  = blockIdx.z;
    const int q0 = qt * 128;

    const size_t base = (size_t)(b * NH + h) * T_SEQ * HS;
    const float* Qg = g_q + base;
    const float* Kg = g_k + base;
    const float* Vg = g_v + base;

    const int tid = threadIdx.x;
    const int tq  = tid >> 4;   // 0..15 : 8 query rows each
    const int tk  = tid & 15;   // 0..15 : 8 key cols (S) / 4 dims (PV)

    // ---- load Q tile transposed, pre-scaled by 1/sqrt(64) ----
#pragma unroll
    for (int i = 0; i < 8; i++) {
        int idx = tid + i * 256;            // 2048 float4-slots? no: 2048 float4s total/…
        int r = idx >> 4;                   // 0..127
        int c = (idx & 15) * 4;             // 0..60
        float4 t = *(const float4*)(Qg + (size_t)(q0 + r) * HS + c);
        Qt[(c + 0) * 132 + r] = t.x * 0.125f;
        Qt[(c + 1) * 132 + r] = t.y * 0.125f;
        Qt[(c + 2) * 132 + r] = t.z * 0.125f;
        Qt[(c + 3) * 132 + r] = t.w * 0.125f;
    }

    float o[8][4];
#pragma unroll
    for (int i = 0; i < 8; i++)
#pragma unroll
        for (int j = 0; j < 4; j++) o[i][j] = 0.0f;
    float mrow[8], lrow[8];
#pragma unroll
    for (int i = 0; i < 8; i++) { mrow[i] = -1e30f; lrow[i] = 0.0f; }

    for (int kt = 0; kt <= qt; kt++) {
        __syncthreads();   // prior readers of Kt/Vs/Ps done (also covers Qt, iter 0)

        // ---- load K (transposed) and V tiles ----
#pragma unroll
        for (int i = 0; i < 8; i++) {
            int idx = tid + i * 256;
            int r = idx >> 4;
            int c = (idx & 15) * 4;
            const float* kp = Kg + (size_t)(kt * 128 + r) * HS + c;
            float4 tK = *(const float4*)kp;
            Kt[(c + 0) * 132 + r] = tK.x;
            Kt[(c + 1) * 132 + r] = tK.y;
            Kt[(c + 2) * 132 + r] = tK.z;
            Kt[(c + 3) * 132 + r] = tK.w;
            float4 tV = *(const float4*)(Vg + (size_t)(kt * 128 + r) * HS + c);
            *(float4*)&Vs[r * 68 + c] = tV;
        }
        __syncthreads();

        // ---- S = Q @ K^T  (8x8 per thread, fully vectorized operands) ----
        float s[8][8];
#pragma unroll
        for (int i = 0; i < 8; i++)
#pragma unroll
            for (int j = 0; j < 8; j++) s[i][j] = 0.0f;

#pragma unroll 4
        for (int d = 0; d < HS; d++) {
            float4 x0 = *(const float4*)&Qt[d * 132 + tq * 8];
            float4 x1 = *(const float4*)&Qt[d * 132 + tq * 8 + 4];
            float4 y0 = *(const float4*)&Kt[d * 132 + tk * 8];
            float4 y1 = *(const float4*)&Kt[d * 132 + tk * 8 + 4];
            float a[8]  = {x0.x, x0.y, x0.z, x0.w, x1.x, x1.y, x1.z, x1.w};
            float bb[8] = {y0.x, y0.y, y0.z, y0.w, y1.x, y1.y, y1.z, y1.w};
#pragma unroll
            for (int i = 0; i < 8; i++)
#pragma unroll
                for (int j = 0; j < 8; j++)
                    s[i][j] = fmaf(a[i], bb[j], s[i][j]);
        }

        // ---- causal mask on diagonal tile ----
        if (kt == qt) {
#pragma unroll
            for (int i = 0; i < 8; i++)
#pragma unroll
                for (int j = 0; j < 8; j++)
                    if (tk * 8 + j > tq * 8 + i) s[i][j] = -1e30f;
        }

        // ---- online softmax (16-lane row groups, warp-aligned) ----
#pragma unroll
        for (int i = 0; i < 8; i++) {
            float mt = s[i][0];
#pragma unroll
            for (int j = 1; j < 8; j++) mt = fmaxf(mt, s[i][j]);
#pragma unroll
            for (int off = 1; off < 16; off <<= 1)
                mt = fmaxf(mt, __shfl_xor_sync(0xffffffffu, mt, off));
            float mnew  = fmaxf(mrow[i], mt);
            float scale = __expf(mrow[i] - mnew);
            mrow[i] = mnew;
            float ssum = 0.0f;
#pragma unroll
            for (int j = 0; j < 8; j++) {
                float p = __expf(s[i][j] - mnew);
                s[i][j] = p;
                ssum += p;
            }
#pragma unroll
            for (int off = 1; off < 16; off <<= 1)
                ssum += __shfl_xor_sync(0xffffffffu, ssum, off);
            lrow[i] = lrow[i] * scale + ssum;
#pragma unroll
            for (int j = 0; j < 4; j++) o[i][j] *= scale;
        }

        // ---- write P (vectorized) ----
#pragma unroll
        for (int i = 0; i < 8; i++) {
            float* pr = &Ps[(tq * 8 + i) * 132 + tk * 8];
            *(float4*)pr       = make_float4(s[i][0], s[i][1], s[i][2], s[i][3]);
            *(float4*)(pr + 4) = make_float4(s[i][4], s[i][5], s[i][6], s[i][7]);
        }
        __syncthreads();

        // ---- O += P @ V  (8 rows x 4 dims; P reads are broadcasts) ----
#pragma unroll 4
        for (int kk = 0; kk < 128; kk++) {
            float pa[8];
#pragma unroll
            for (int i = 0; i < 8; i++) pa[i] = Ps[(tq * 8 + i) * 132 + kk];
            float4 v = *(const float4*)&Vs[kk * 68 + tk * 4];
            float vb[4] = {v.x, v.y, v.z, v.w};
#pragma unroll
            for (int i = 0; i < 8; i++)
#pragma unroll
                for (int j = 0; j < 4; j++)
                    o[i][j] = fmaf(pa[i], vb[j], o[i][j]);
        }
    }

    // ---- normalize and write to g_att [b][t][h*64+d] ----
#pragma unroll
    for (int i = 0; i < 8; i++) {
        float inv = 1.0f / lrow[i];
        int t = q0 + tq * 8 + i;
        float* dst = g_att + ((size_t)(b * T_SEQ + t)) * CEMB + h * HS + tk * 4;
        float4 ov = make_float4(o[i][0] * inv, o[i][1] * inv,
                                o[i][2] * inv, o[i][3] * inv);
        *(float4*)dst = ov;
    }
}

// ============================================================================
// launch
// ============================================================================
extern "C" void kernel_launch(void* const* d_in, const int* in_sizes, int n_in,
                              void* d_out, int out_size)
{
    const float* x    = (const float*)d_in[0];
    const float* Wqkv = (const float*)d_in[1];
    const float* bqkv = (const float*)d_in[2];
    const float* Wo   = (const float*)d_in[3];
    const float* bo   = (const float*)d_in[4];
    float* out = (float*)d_out;

    constexpr int ATTN_SMEM = (64 * 132 + 64 * 132 + 128 * 68 + 128 * 132) * 4;
    cudaFuncSetAttribute(attn2, cudaFuncAttributeMaxDynamicSharedMemorySize,
                         ATTN_SMEM);

    // 1) QKV projection + scatter to g_q/g_k/g_v
    sgemm2<0><<<dim3(C3 / 128, (NB * T_SEQ) / 128), 256>>>(x, Wqkv, bqkv, nullptr, C3);

    // 2) causal flash attention -> g_att
    attn2<<<dim3(T_SEQ / 128, NH, NB), 256, ATTN_SMEM>>>();

    // 3) output projection -> d_out
    sgemm2<1><<<dim3(CEMB / 128, (NB * T_SEQ) / 128), 256>>>(nullptr, Wo, bo, out, CEMB);
}

// round 9
// speedup vs baseline: 1.6373x; 1.4328x over previous
#include <cuda_runtime.h>
#include <cuda_bf16.h>
#include <cstdint>

// ---------------- problem constants ----------------
#define T_SEQ 2048
#define NB    2
#define NH    16
#define HS    64
#define CEMB  1024
#define C3    3072
#define MTOT  (NB * T_SEQ)   // 4096

// ---------------- device scratch: 64 MiB total (round-4-proven footprint) --
__device__ float g_q[NB * NH * T_SEQ * HS];     // 16 MiB
__device__ float g_k[NB * NH * T_SEQ * HS];     // 16 MiB
__device__ float g_v[NB * NH * T_SEQ * HS];     // 16 MiB
__device__ float g_att[MTOT * CEMB];            // 16 MiB  [b*T+t][h*64+d]

// ============================================================================
// helpers
// ============================================================================
__device__ __forceinline__ uint32_t smem_u32(const void* p) {
    uint32_t a;
    asm("{ .reg .u64 t; cvta.to.shared.u64 t, %1; cvt.u32.u64 %0, t; }"
        : "=r"(a) : "l"(p));
    return a;
}
__device__ __forceinline__ void split2(float v, __nv_bfloat16& h, __nv_bfloat16& l) {
    h = __float2bfloat16(v);
    l = __float2bfloat16(v - __bfloat162float(h));
}

__device__ __forceinline__ void ldm_x4(uint32_t addr, uint32_t r[4]) {
    asm volatile("ldmatrix.sync.aligned.m8n8.x4.shared.b16 {%0,%1,%2,%3}, [%4];"
        : "=r"(r[0]), "=r"(r[1]), "=r"(r[2]), "=r"(r[3]) : "r"(addr));
}
__device__ __forceinline__ void ldm_x4t(uint32_t addr, uint32_t r[4]) {
    asm volatile("ldmatrix.sync.aligned.m8n8.x4.trans.shared.b16 {%0,%1,%2,%3}, [%4];"
        : "=r"(r[0]), "=r"(r[1]), "=r"(r[2]), "=r"(r[3]) : "r"(addr));
}
__device__ __forceinline__ void mma16816(float c[4], const uint32_t a[4],
                                         const uint32_t b[2]) {
    asm volatile(
        "mma.sync.aligned.m16n8k16.row.col.f32.bf16.bf16.f32 "
        "{%0,%1,%2,%3}, {%4,%5,%6,%7}, {%8,%9}, {%0,%1,%2,%3};"
        : "+f"(c[0]), "+f"(c[1]), "+f"(c[2]), "+f"(c[3])
        : "r"(a[0]), "r"(a[1]), "r"(a[2]), "r"(a[3]), "r"(b[0]), "r"(b[1]));
}

// ============================================================================
// warp-MMA bf16x3 GEMM with INLINE fp32 -> split-bf16 conversion.
//   C[M-tile, N-tile] = A[M,1024] @ W[1024,N] + bias
// CTA tile 128x128, BK=64, 8 warps (warp tile 64x32), single smem buffer,
// serialized fill/MMA phases. Split trick: C ≈ AhiWhi + AloWhi + AhiWlo
// (fp32 accum; AloWlo term ~2^-18 relative, negligible vs 1e-3 gate).
//
// smem: A_hi[128][72 bf16] (144 B rows), A_lo same;  k-contiguous, plain
//       ldmatrix (A fragment). W_hi[64][136 bf16] (272 B rows), W_lo same;
//       n-contiguous, ldmatrix.trans (B fragment). Total 71,680 B.
// MODE 0: A = x, epilogue scatters into g_q/g_k/g_v  (N = 3072)
// MODE 1: A = g_att, epilogue writes Cout + bias     (N = 1024)
// ============================================================================
#define A_TILE 18432             // 128 * 144
#define B_TILE 17408             // 64 * 272
#define GEMM_SMEM (2 * A_TILE + 2 * B_TILE)   // 71,680 B

template <int MODE>
__global__ void __launch_bounds__(256, 1)
mma_gemm(const float* __restrict__ Aglob, const float* __restrict__ W,
         const float* __restrict__ bias, float* __restrict__ Cout, int N)
{
    extern __shared__ char smem[];
    const uint32_t sA_hi = smem_u32(smem);
    const uint32_t sA_lo = sA_hi + A_TILE;
    const uint32_t sB_hi = sA_hi + 2 * A_TILE;
    const uint32_t sB_lo = sB_hi + B_TILE;
    char* pA_hi = smem;
    char* pA_lo = smem + A_TILE;
    char* pB_hi = smem + 2 * A_TILE;
    char* pB_lo = pB_hi + B_TILE;

    const int tid  = threadIdx.x;
    const int lane = tid & 31;
    const int wid  = tid >> 5;
    const int m0   = blockIdx.y * 128;
    const int n0   = blockIdx.x * 128;
    const int wm0  = (wid & 1) * 64;
    const int wn0  = (wid >> 1) * 32;

    const float* A = (MODE == 0) ? Aglob : (const float*)g_att;

    float acc[4][4][4];
#pragma unroll
    for (int mt = 0; mt < 4; mt++)
#pragma unroll
        for (int nt = 0; nt < 4; nt++)
#pragma unroll
            for (int e = 0; e < 4; e++) acc[mt][nt][e] = 0.0f;

    // ldmatrix lane addressing
    const int a_row = lane & 15;                       // m row 0..15
    const int a_cb  = (lane >> 4) * 16;                // k half (bytes)
    const int b_krow = ((lane >> 3) & 1) * 8 + (lane & 7);   // k row 0..15
    const int b_nb   = (lane >> 4) * 16;               // n half (bytes)

    const uint32_t aBase = sA_hi + (uint32_t)((wm0 + a_row) * 144 + a_cb);
    const uint32_t bBase = sB_hi + (uint32_t)(b_krow * 272 + wn0 * 2 + b_nb);

    constexpr int NKT = CEMB / 64;   // 16
    for (int kt = 0; kt < NKT; kt++) {
        __syncthreads();   // previous chunk's MMAs done reading smem

        // ---- fill A tiles: 128 m x 64 k fp32 -> split bf16 (k-contiguous) --
#pragma unroll
        for (int j = 0; j < 8; j++) {
            const int idx = tid + j * 256;        // 0..2047
            const int m = idx >> 4;
            const int c = idx & 15;               // float4 within k
            float4 v = *(const float4*)(A + (size_t)(m0 + m) * CEMB + kt * 64 + c * 4);
            __nv_bfloat16 h0, h1, h2, h3, l0, l1, l2, l3;
            split2(v.x, h0, l0); split2(v.y, h1, l1);
            split2(v.z, h2, l2); split2(v.w, h3, l3);
            __nv_bfloat162 hA, hB, lA, lB;
            hA.x = h0; hA.y = h1; hB.x = h2; hB.y = h3;
            lA.x = l0; lA.y = l1; lB.x = l2; lB.y = l3;
            const int so = m * 144 + c * 8;
            *(__nv_bfloat162*)(pA_hi + so)     = hA;
            *(__nv_bfloat162*)(pA_hi + so + 4) = hB;
            *(__nv_bfloat162*)(pA_lo + so)     = lA;
            *(__nv_bfloat162*)(pA_lo + so + 4) = lB;
        }
        // ---- fill W tiles: 64 k x 128 n fp32 -> split bf16 (n-contiguous) --
#pragma unroll
        for (int j = 0; j < 8; j++) {
            const int idx = tid + j * 256;        // 0..2047
            const int k = idx >> 5;
            const int c = idx & 31;               // float4 within n
            float4 v = *(const float4*)(W + (size_t)(kt * 64 + k) * N + n0 + c * 4);
            __nv_bfloat16 h0, h1, h2, h3, l0, l1, l2, l3;
            split2(v.x, h0, l0); split2(v.y, h1, l1);
            split2(v.z, h2, l2); split2(v.w, h3, l3);
            __nv_bfloat162 hA, hB, lA, lB;
            hA.x = h0; hA.y = h1; hB.x = h2; hB.y = h3;
            lA.x = l0; lA.y = l1; lB.x = l2; lB.y = l3;
            const int so = k * 272 + c * 8;
            *(__nv_bfloat162*)(pB_hi + so)     = hA;
            *(__nv_bfloat162*)(pB_hi + so + 4) = hB;
            *(__nv_bfloat162*)(pB_lo + so)     = lA;
            *(__nv_bfloat162*)(pB_lo + so + 4) = lB;
        }
        __syncthreads();

        // ---- MMA phase: 4 k-steps of 16 ----
#pragma unroll
        for (int ks = 0; ks < 4; ks++) {
            uint32_t bhi[2][4], blo[2][4];
#pragma unroll
            for (int g = 0; g < 2; g++) {
                const uint32_t bd = bBase + (uint32_t)(ks * 16 * 272 + g * 32);
                ldm_x4t(bd, bhi[g]);
                ldm_x4t(bd + B_TILE, blo[g]);
            }
#pragma unroll
            for (int mt = 0; mt < 4; mt++) {
                uint32_t ahi[4], alo[4];
                const uint32_t ad = aBase + (uint32_t)(mt * 16 * 144 + ks * 32);
                ldm_x4(ad, ahi);
                ldm_x4(ad + A_TILE, alo);
#pragma unroll
                for (int g = 0; g < 2; g++)
#pragma unroll
                    for (int h2 = 0; h2 < 2; h2++) {
                        const int nt = g * 2 + h2;
                        mma16816(acc[mt][nt], ahi, &bhi[g][h2 * 2]);
                        mma16816(acc[mt][nt], alo, &bhi[g][h2 * 2]);
                        mma16816(acc[mt][nt], ahi, &blo[g][h2 * 2]);
                    }
            }
        }
    }

    // ---------------- epilogue ----------------
    // D frag: c0,c1 -> (row = lane/4, col = 2*(lane%4)+{0,1}); c2,c3 -> row+8
#pragma unroll
    for (int mt = 0; mt < 4; mt++) {
        const int mrow = m0 + wm0 + mt * 16 + (lane >> 2);
#pragma unroll
        for (int nt = 0; nt < 4; nt++) {
            const int nb = n0 + wn0 + nt * 8 + (lane & 3) * 2;
            const float b0 = bias[nb], b1 = bias[nb + 1];
            const float* a = acc[mt][nt];
            if (MODE == 0) {
                const int hh = nb / 192;
                const int e  = nb - hh * 192;
                const int wh = e >> 6;
                const int d0 = e & 63;
                float* arr = (wh == 0) ? g_q : (wh == 1) ? g_k : g_v;
                const int bi = mrow >> 11;
                const int t  = mrow & (T_SEQ - 1);
                float* dst0 = arr + ((size_t)((bi * NH + hh) * T_SEQ + t)) * HS + d0;
                *(float2*)dst0 = make_float2(a[0] + b0, a[1] + b1);
                float* dst1 = arr + ((size_t)((bi * NH + hh) * T_SEQ + t + 8)) * HS + d0;
                *(float2*)dst1 = make_float2(a[2] + b0, a[3] + b1);
            } else {
                float* dst0 = Cout + (size_t)mrow * N + nb;
                *(float2*)dst0 = make_float2(a[0] + b0, a[1] + b1);
                float* dst1 = Cout + (size_t)(mrow + 8) * N + nb;
                *(float2*)dst1 = make_float2(a[2] + b0, a[3] + b1);
            }
        }
    }
}

// ============================================================================
// Causal flash attention, fp32 (round-4-proven kernel, fp32 g_att output).
// ============================================================================
__global__ void __launch_bounds__(256)
attn2(void)
{
    extern __shared__ float sm[];
    float* Qt = sm;                     // [64][132]
    float* Kt = Qt + 64 * 132;          // [64][132]
    float* Vs = Kt + 64 * 132;          // [128][68]
    float* Ps = Vs + 128 * 68;          // [128][132]

    const int qt = gridDim.x - 1 - blockIdx.x;
    const int h  = blockIdx.y;
    const int b  = blockIdx.z;
    const int q0 = qt * 128;

    const size_t base = (size_t)(b * NH + h) * T_SEQ * HS;
    const float* Qg = g_q + base;
    const float* Kg = g_k + base;
    const float* Vg = g_v + base;

    const int tid = threadIdx.x;
    const int tq  = tid >> 4;
    const int tk  = tid & 15;

#pragma unroll
    for (int i = 0; i < 8; i++) {
        int idx = tid + i * 256;
        int r = idx >> 4;
        int c = (idx & 15) * 4;
        float4 t = *(const float4*)(Qg + (size_t)(q0 + r) * HS + c);
        Qt[(c + 0) * 132 + r] = t.x * 0.125f;
        Qt[(c + 1) * 132 + r] = t.y * 0.125f;
        Qt[(c + 2) * 132 + r] = t.z * 0.125f;
        Qt[(c + 3) * 132 + r] = t.w * 0.125f;
    }

    float o[8][4];
#pragma unroll
    for (int i = 0; i < 8; i++)
#pragma unroll
        for (int j = 0; j < 4; j++) o[i][j] = 0.0f;
    float mrow[8], lrow[8];
#pragma unroll
    for (int i = 0; i < 8; i++) { mrow[i] = -1e30f; lrow[i] = 0.0f; }

    for (int kt = 0; kt <= qt; kt++) {
        __syncthreads();
#pragma unroll
        for (int i = 0; i < 8; i++) {
            int idx = tid + i * 256;
            int r = idx >> 4;
            int c = (idx & 15) * 4;
            float4 tK = *(const float4*)(Kg + (size_t)(kt * 128 + r) * HS + c);
            Kt[(c + 0) * 132 + r] = tK.x;
            Kt[(c + 1) * 132 + r] = tK.y;
            Kt[(c + 2) * 132 + r] = tK.z;
            Kt[(c + 3) * 132 + r] = tK.w;
            float4 tV = *(const float4*)(Vg + (size_t)(kt * 128 + r) * HS + c);
            *(float4*)&Vs[r * 68 + c] = tV;
        }
        __syncthreads();

        float s[8][8];
#pragma unroll
        for (int i = 0; i < 8; i++)
#pragma unroll
            for (int j = 0; j < 8; j++) s[i][j] = 0.0f;

#pragma unroll 4
        for (int d = 0; d < HS; d++) {
            float4 x0 = *(const float4*)&Qt[d * 132 + tq * 8];
            float4 x1 = *(const float4*)&Qt[d * 132 + tq * 8 + 4];
            float4 y0 = *(const float4*)&Kt[d * 132 + tk * 8];
            float4 y1 = *(const float4*)&Kt[d * 132 + tk * 8 + 4];
            float a[8]  = {x0.x, x0.y, x0.z, x0.w, x1.x, x1.y, x1.z, x1.w};
            float bb[8] = {y0.x, y0.y, y0.z, y0.w, y1.x, y1.y, y1.z, y1.w};
#pragma unroll
            for (int i = 0; i < 8; i++)
#pragma unroll
                for (int j = 0; j < 8; j++)
                    s[i][j] = fmaf(a[i], bb[j], s[i][j]);
        }

        if (kt == qt) {
#pragma unroll
            for (int i = 0; i < 8; i++)
#pragma unroll
                for (int j = 0; j < 8; j++)
                    if (tk * 8 + j > tq * 8 + i) s[i][j] = -1e30f;
        }

#pragma unroll
        for (int i = 0; i < 8; i++) {
            float mt = s[i][0];
#pragma unroll
            for (int j = 1; j < 8; j++) mt = fmaxf(mt, s[i][j]);
#pragma unroll
            for (int off = 1; off < 16; off <<= 1)
                mt = fmaxf(mt, __shfl_xor_sync(0xffffffffu, mt, off));
            float mnew  = fmaxf(mrow[i], mt);
            float scale = __expf(mrow[i] - mnew);
            mrow[i] = mnew;
            float ssum = 0.0f;
#pragma unroll
            for (int j = 0; j < 8; j++) {
                float p = __expf(s[i][j] - mnew);
                s[i][j] = p;
                ssum += p;
            }
#pragma unroll
            for (int off = 1; off < 16; off <<= 1)
                ssum += __shfl_xor_sync(0xffffffffu, ssum, off);
            lrow[i] = lrow[i] * scale + ssum;
#pragma unroll
            for (int j = 0; j < 4; j++) o[i][j] *= scale;
        }

#pragma unroll
        for (int i = 0; i < 8; i++) {
            float* pr = &Ps[(tq * 8 + i) * 132 + tk * 8];
            *(float4*)pr       = make_float4(s[i][0], s[i][1], s[i][2], s[i][3]);
            *(float4*)(pr + 4) = make_float4(s[i][4], s[i][5], s[i][6], s[i][7]);
        }
        __syncthreads();

#pragma unroll 4
        for (int kk = 0; kk < 128; kk++) {
            float pa[8];
#pragma unroll
            for (int i = 0; i < 8; i++) pa[i] = Ps[(tq * 8 + i) * 132 + kk];
            float4 v = *(const float4*)&Vs[kk * 68 + tk * 4];
            float vb[4] = {v.x, v.y, v.z, v.w};
#pragma unroll
            for (int i = 0; i < 8; i++)
#pragma unroll
                for (int j = 0; j < 4; j++)
                    o[i][j] = fmaf(pa[i], vb[j], o[i][j]);
        }
    }

    // ---- normalize and write fp32 to g_att [b*T+t][h*64+d] ----
#pragma unroll
    for (int i = 0; i < 8; i++) {
        float inv = 1.0f / lrow[i];
        int t = q0 + tq * 8 + i;
        float* dst = g_att + ((size_t)(b * T_SEQ + t)) * CEMB + h * HS + tk * 4;
        *(float4*)dst = make_float4(o[i][0] * inv, o[i][1] * inv,
                                    o[i][2] * inv, o[i][3] * inv);
    }
}

// ============================================================================
// launch
// ============================================================================
extern "C" void kernel_launch(void* const* d_in, const int* in_sizes, int n_in,
                              void* d_out, int out_size)
{
    const float* x    = (const float*)d_in[0];
    const float* Wqkv = (const float*)d_in[1];
    const float* bqkv = (const float*)d_in[2];
    const float* Wo   = (const float*)d_in[3];
    const float* bo   = (const float*)d_in[4];
    float* out = (float*)d_out;

    constexpr int ATTN_SMEM = (64 * 132 + 64 * 132 + 128 * 68 + 128 * 132) * 4;
    cudaFuncSetAttribute(attn2, cudaFuncAttributeMaxDynamicSharedMemorySize, ATTN_SMEM);
    cudaFuncSetAttribute(mma_gemm<0>, cudaFuncAttributeMaxDynamicSharedMemorySize, GEMM_SMEM);
    cudaFuncSetAttribute(mma_gemm<1>, cudaFuncAttributeMaxDynamicSharedMemorySize, GEMM_SMEM);

    // 1) QKV projection (mma.sync bf16x3, inline split) -> g_q/g_k/g_v
    mma_gemm<0><<<dim3(C3 / 128, MTOT / 128), 256, GEMM_SMEM>>>(x, Wqkv, bqkv, nullptr, C3);

    // 2) causal flash attention -> g_att (fp32)
    attn2<<<dim3(T_SEQ / 128, NH, NB), 256, ATTN_SMEM>>>();

    // 3) output projection (mma.sync bf16x3, inline split) -> d_out
    mma_gemm<1><<<dim3(CEMB / 128, MTOT / 128), 256, GEMM_SMEM>>>(nullptr, Wo, bo, out, CEMB);
}

// round 10
// speedup vs baseline: 2.6413x; 1.6132x over previous
#include <cuda_runtime.h>
#include <cuda_bf16.h>
#include <cstdint>

// ---------------- problem constants ----------------
#define T_SEQ 2048
#define NB    2
#define NH    16
#define HS    64
#define CEMB  1024
#define C3    3072
#define MTOT  (NB * T_SEQ)   // 4096

// ---------------- device scratch: 64 MiB total (proven-safe footprint) ----
__device__ float g_q[NB * NH * T_SEQ * HS];     // 16 MiB
__device__ float g_k[NB * NH * T_SEQ * HS];     // 16 MiB
__device__ float g_v[NB * NH * T_SEQ * HS];     // 16 MiB
__device__ float g_att[MTOT * CEMB];            // 16 MiB  [b*T+t][h*64+d]

// ============================================================================
// helpers
// ============================================================================
__device__ __forceinline__ uint32_t smem_u32(const void* p) {
    uint32_t a;
    asm("{ .reg .u64 t; cvta.to.shared.u64 t, %1; cvt.u32.u64 %0, t; }"
        : "=r"(a) : "l"(p));
    return a;
}
__device__ __forceinline__ void split2(float v, __nv_bfloat16& h, __nv_bfloat16& l) {
    h = __float2bfloat16(v);
    l = __float2bfloat16(v - __bfloat162float(h));
}
__device__ __forceinline__ uint32_t pack_hi(float a, float b) {
    __nv_bfloat162 t;
    t.x = __float2bfloat16(a);
    t.y = __float2bfloat16(b);
    return *(uint32_t*)&t;
}
__device__ __forceinline__ uint32_t pack_lo(float a, float b) {
    __nv_bfloat16 ha = __float2bfloat16(a);
    __nv_bfloat16 hb = __float2bfloat16(b);
    __nv_bfloat162 t;
    t.x = __float2bfloat16(a - __bfloat162float(ha));
    t.y = __float2bfloat16(b - __bfloat162float(hb));
    return *(uint32_t*)&t;
}

__device__ __forceinline__ void ldm_x4(uint32_t addr, uint32_t r[4]) {
    asm volatile("ldmatrix.sync.aligned.m8n8.x4.shared.b16 {%0,%1,%2,%3}, [%4];"
        : "=r"(r[0]), "=r"(r[1]), "=r"(r[2]), "=r"(r[3]) : "r"(addr));
}
__device__ __forceinline__ void ldm_x4t(uint32_t addr, uint32_t r[4]) {
    asm volatile("ldmatrix.sync.aligned.m8n8.x4.trans.shared.b16 {%0,%1,%2,%3}, [%4];"
        : "=r"(r[0]), "=r"(r[1]), "=r"(r[2]), "=r"(r[3]) : "r"(addr));
}
__device__ __forceinline__ void mma16816(float c[4], const uint32_t a[4],
                                         const uint32_t b[2]) {
    asm volatile(
        "mma.sync.aligned.m16n8k16.row.col.f32.bf16.bf16.f32 "
        "{%0,%1,%2,%3}, {%4,%5,%6,%7}, {%8,%9}, {%0,%1,%2,%3};"
        : "+f"(c[0]), "+f"(c[1]), "+f"(c[2]), "+f"(c[3])
        : "r"(a[0]), "r"(a[1]), "r"(a[2]), "r"(a[3]), "r"(b[0]), "r"(b[1]));
}

// ============================================================================
// warp-MMA bf16x3 GEMM with inline fp32 -> split-bf16 conversion
// (UNCHANGED from the passing round-8 kernel).
// ============================================================================
#define A_TILE 18432             // 128 * 144
#define B_TILE 17408             // 64 * 272
#define GEMM_SMEM (2 * A_TILE + 2 * B_TILE)   // 71,680 B

template <int MODE>
__global__ void __launch_bounds__(256, 1)
mma_gemm(const float* __restrict__ Aglob, const float* __restrict__ W,
         const float* __restrict__ bias, float* __restrict__ Cout, int N)
{
    extern __shared__ char smem[];
    const uint32_t sA_hi = smem_u32(smem);
    const uint32_t sB_hi = sA_hi + 2 * A_TILE;
    char* pA_hi = smem;
    char* pA_lo = smem + A_TILE;
    char* pB_hi = smem + 2 * A_TILE;
    char* pB_lo = pB_hi + B_TILE;

    const int tid  = threadIdx.x;
    const int lane = tid & 31;
    const int wid  = tid >> 5;
    const int m0   = blockIdx.y * 128;
    const int n0   = blockIdx.x * 128;
    const int wm0  = (wid & 1) * 64;
    const int wn0  = (wid >> 1) * 32;

    const float* A = (MODE == 0) ? Aglob : (const float*)g_att;

    float acc[4][4][4];
#pragma unroll
    for (int mt = 0; mt < 4; mt++)
#pragma unroll
        for (int nt = 0; nt < 4; nt++)
#pragma unroll
            for (int e = 0; e < 4; e++) acc[mt][nt][e] = 0.0f;

    const int a_row = lane & 15;
    const int a_cb  = (lane >> 4) * 16;
    const int b_krow = ((lane >> 3) & 1) * 8 + (lane & 7);
    const int b_nb   = (lane >> 4) * 16;

    const uint32_t aBase = sA_hi + (uint32_t)((wm0 + a_row) * 144 + a_cb);
    const uint32_t bBase = sB_hi + (uint32_t)(b_krow * 272 + wn0 * 2 + b_nb);

    constexpr int NKT = CEMB / 64;   // 16
    for (int kt = 0; kt < NKT; kt++) {
        __syncthreads();
#pragma unroll
        for (int j = 0; j < 8; j++) {
            const int idx = tid + j * 256;
            const int m = idx >> 4;
            const int c = idx & 15;
            float4 v = *(const float4*)(A + (size_t)(m0 + m) * CEMB + kt * 64 + c * 4);
            __nv_bfloat16 h0, h1, h2, h3, l0, l1, l2, l3;
            split2(v.x, h0, l0); split2(v.y, h1, l1);
            split2(v.z, h2, l2); split2(v.w, h3, l3);
            __nv_bfloat162 hA, hB, lA, lB;
            hA.x = h0; hA.y = h1; hB.x = h2; hB.y = h3;
            lA.x = l0; lA.y = l1; lB.x = l2; lB.y = l3;
            const int so = m * 144 + c * 8;
            *(__nv_bfloat162*)(pA_hi + so)     = hA;
            *(__nv_bfloat162*)(pA_hi + so + 4) = hB;
            *(__nv_bfloat162*)(pA_lo + so)     = lA;
            *(__nv_bfloat162*)(pA_lo + so + 4) = lB;
        }
#pragma unroll
        for (int j = 0; j < 8; j++) {
            const int idx = tid + j * 256;
            const int k = idx >> 5;
            const int c = idx & 31;
            float4 v = *(const float4*)(W + (size_t)(kt * 64 + k) * N + n0 + c * 4);
            __nv_bfloat16 h0, h1, h2, h3, l0, l1, l2, l3;
            split2(v.x, h0, l0); split2(v.y, h1, l1);
            split2(v.z, h2, l2); split2(v.w, h3, l3);
            __nv_bfloat162 hA, hB, lA, lB;
            hA.x = h0; hA.y = h1; hB.x = h2; hB.y = h3;
            lA.x = l0; lA.y = l1; lB.x = l2; lB.y = l3;
            const int so = k * 272 + c * 8;
            *(__nv_bfloat162*)(pB_hi + so)     = hA;
            *(__nv_bfloat162*)(pB_hi + so + 4) = hB;
            *(__nv_bfloat162*)(pB_lo + so)     = lA;
            *(__nv_bfloat162*)(pB_lo + so + 4) = lB;
        }
        __syncthreads();

#pragma unroll
        for (int ks = 0; ks < 4; ks++) {
            uint32_t bhi[2][4], blo[2][4];
#pragma unroll
            for (int g = 0; g < 2; g++) {
                const uint32_t bd = bBase + (uint32_t)(ks * 16 * 272 + g * 32);
                ldm_x4t(bd, bhi[g]);
                ldm_x4t(bd + B_TILE, blo[g]);
            }
#pragma unroll
            for (int mt = 0; mt < 4; mt++) {
                uint32_t ahi[4], alo[4];
                const uint32_t ad = aBase + (uint32_t)(mt * 16 * 144 + ks * 32);
                ldm_x4(ad, ahi);
                ldm_x4(ad + A_TILE, alo);
#pragma unroll
                for (int g = 0; g < 2; g++)
#pragma unroll
                    for (int h2 = 0; h2 < 2; h2++) {
                        const int nt = g * 2 + h2;
                        mma16816(acc[mt][nt], ahi, &bhi[g][h2 * 2]);
                        mma16816(acc[mt][nt], alo, &bhi[g][h2 * 2]);
                        mma16816(acc[mt][nt], ahi, &blo[g][h2 * 2]);
                    }
            }
        }
    }

#pragma unroll
    for (int mt = 0; mt < 4; mt++) {
        const int mrow = m0 + wm0 + mt * 16 + (lane >> 2);
#pragma unroll
        for (int nt = 0; nt < 4; nt++) {
            const int nb = n0 + wn0 + nt * 8 + (lane & 3) * 2;
            const float b0 = bias[nb], b1 = bias[nb + 1];
            const float* a = acc[mt][nt];
            if (MODE == 0) {
                const int hh = nb / 192;
                const int e  = nb - hh * 192;
                const int wh = e >> 6;
                const int d0 = e & 63;
                float* arr = (wh == 0) ? g_q : (wh == 1) ? g_k : g_v;
                const int bi = mrow >> 11;
                const int t  = mrow & (T_SEQ - 1);
                float* dst0 = arr + ((size_t)((bi * NH + hh) * T_SEQ + t)) * HS + d0;
                *(float2*)dst0 = make_float2(a[0] + b0, a[1] + b1);
                float* dst1 = arr + ((size_t)((bi * NH + hh) * T_SEQ + t + 8)) * HS + d0;
                *(float2*)dst1 = make_float2(a[2] + b0, a[3] + b1);
            } else {
                float* dst0 = Cout + (size_t)mrow * N + nb;
                *(float2*)dst0 = make_float2(a[0] + b0, a[1] + b1);
                float* dst1 = Cout + (size_t)(mrow + 8) * N + nb;
                *(float2*)dst1 = make_float2(a[2] + b0, a[3] + b1);
            }
        }
    }
}

// ============================================================================
// Causal flash attention on mma.sync bf16x3.
// CTA = (q-tile 128, head, batch); 8 warps; warp owns 16 q-rows x all 128 kv.
// smem (110,592 B): Q_hi/Q_lo [128][72bf16]s144, K_hi/K_lo [128 t][72]s144
// (natural [n][k] for B), V_hi/V_lo [128 t][72]s144 ([k][n], ldmatrix.trans).
// S D-fragments repacked in registers as P A-fragments (lane-exact match).
// Softmax: 4-lane shfl row reductions (lanes 4q..4q+3 share a row).
// ============================================================================
#define QOFF 0
#define KOFF (2 * 18432)
#define VOFF (4 * 18432)
#define ATTN_SMEM (6 * 18432)    // 110,592 B

__device__ __forceinline__ void fill_split_qkv(const float* __restrict__ src,
                                               char* __restrict__ hi,
                                               char* __restrict__ lo,
                                               int tid, float scl)
{
    // 128 rows x 64 fp32 (row stride HS) -> hi/lo bf16, smem stride 144
#pragma unroll
    for (int j = 0; j < 8; j++) {
        const int idx = tid + j * 256;
        const int m = idx >> 4;
        const int c = idx & 15;
        float4 v = *(const float4*)(src + (size_t)m * HS + c * 4);
        v.x *= scl; v.y *= scl; v.z *= scl; v.w *= scl;
        __nv_bfloat16 h0, h1, h2, h3, l0, l1, l2, l3;
        split2(v.x, h0, l0); split2(v.y, h1, l1);
        split2(v.z, h2, l2); split2(v.w, h3, l3);
        __nv_bfloat162 hA, hB, lA, lB;
        hA.x = h0; hA.y = h1; hB.x = h2; hB.y = h3;
        lA.x = l0; lA.y = l1; lB.x = l2; lB.y = l3;
        const int so = m * 144 + c * 8;
        *(__nv_bfloat162*)(hi + so)     = hA;
        *(__nv_bfloat162*)(hi + so + 4) = hB;
        *(__nv_bfloat162*)(lo + so)     = lA;
        *(__nv_bfloat162*)(lo + so + 4) = lB;
    }
}

__global__ void __launch_bounds__(256, 1)
attn_mma(void)
{
    extern __shared__ char smem[];
    const uint32_t sbase = smem_u32(smem);
    const int tid  = threadIdx.x;
    const int lane = tid & 31;
    const int wid  = tid >> 5;

    const int qt = gridDim.x - 1 - blockIdx.x;   // heavy q-tiles first
    const int h  = blockIdx.y;
    const int b  = blockIdx.z;
    const int q0 = qt * 128;

    const size_t base = (size_t)(b * NH + h) * T_SEQ * HS;
    const float* Qg = g_q + base + (size_t)q0 * HS;
    const float* Kg = g_k + base;
    const float* Vg = g_v + base;

    // Q: fill once, pre-scaled by 1/sqrt(64)
    fill_split_qkv(Qg, smem + QOFF, smem + QOFF + 18432, tid, 0.125f);

    // ldmatrix bases
    const uint32_t aBase = sbase + QOFF +
        (uint32_t)((wid * 16 + (lane & 15)) * 144 + (lane >> 4) * 16);
    const uint32_t kBase = sbase + KOFF +
        (uint32_t)(((((lane >> 4) << 3) + (lane & 7)) * 144) + ((lane >> 3) & 1) * 16);
    const uint32_t vBase = sbase + VOFF +
        (uint32_t)(((((lane >> 3) & 1) * 8 + (lane & 7)) * 144) + (lane >> 4) * 16);

    float o[8][4];
#pragma unroll
    for (int nt = 0; nt < 8; nt++)
#pragma unroll
        for (int e = 0; e < 4; e++) o[nt][e] = 0.0f;
    float m0 = -1e30f, m1 = -1e30f, l0 = 0.0f, l1 = 0.0f;

    const int rloc0 = wid * 16 + (lane >> 2);    // local q row (0..127)
    const int rloc1 = rloc0 + 8;

    for (int kt = 0; kt <= qt; kt++) {
        __syncthreads();
        fill_split_qkv(Kg + (size_t)(kt * 128) * HS,
                       smem + KOFF, smem + KOFF + 18432, tid, 1.0f);
        fill_split_qkv(Vg + (size_t)(kt * 128) * HS,
                       smem + VOFF, smem + VOFF + 18432, tid, 1.0f);
        __syncthreads();

        // ---- S = Q @ K^T  (16 n-tiles of 8 keys) ----
        float s[16][4];
#pragma unroll
        for (int nt = 0; nt < 16; nt++)
#pragma unroll
            for (int e = 0; e < 4; e++) s[nt][e] = 0.0f;

#pragma unroll
        for (int ks = 0; ks < 4; ks++) {
            uint32_t ahi[4], alo[4];
            ldm_x4(aBase + ks * 32, ahi);
            ldm_x4(aBase + 18432 + ks * 32, alo);
#pragma unroll
            for (int g = 0; g < 8; g++) {
                uint32_t kh[4], kl[4];
                const uint32_t kd = kBase + (uint32_t)(g * 16 * 144 + ks * 32);
                ldm_x4(kd, kh);
                ldm_x4(kd + 18432, kl);
#pragma unroll
                for (int h2 = 0; h2 < 2; h2++) {
                    const int nt = g * 2 + h2;
                    mma16816(s[nt], ahi, &kh[h2 * 2]);
                    mma16816(s[nt], alo, &kh[h2 * 2]);
                    mma16816(s[nt], ahi, &kl[h2 * 2]);
                }
            }
        }

        // ---- causal mask (diagonal tile only) ----
        if (kt == qt) {
#pragma unroll
            for (int nt = 0; nt < 16; nt++) {
                const int c0 = nt * 8 + (lane & 3) * 2;
                const int c1 = c0 + 1;
                if (c0 > rloc0) s[nt][0] = -1e30f;
                if (c1 > rloc0) s[nt][1] = -1e30f;
                if (c0 > rloc1) s[nt][2] = -1e30f;
                if (c1 > rloc1) s[nt][3] = -1e30f;
            }
        }

        // ---- online softmax (rows r0 via c0/c1, r1 via c2/c3) ----
        float mx0 = -1e30f, mx1 = -1e30f;
#pragma unroll
        for (int nt = 0; nt < 16; nt++) {
            mx0 = fmaxf(mx0, fmaxf(s[nt][0], s[nt][1]));
            mx1 = fmaxf(mx1, fmaxf(s[nt][2], s[nt][3]));
        }
        mx0 = fmaxf(mx0, __shfl_xor_sync(0xffffffffu, mx0, 1));
        mx0 = fmaxf(mx0, __shfl_xor_sync(0xffffffffu, mx0, 2));
        mx1 = fmaxf(mx1, __shfl_xor_sync(0xffffffffu, mx1, 1));
        mx1 = fmaxf(mx1, __shfl_xor_sync(0xffffffffu, mx1, 2));

        const float mn0 = fmaxf(m0, mx0);
        const float mn1 = fmaxf(m1, mx1);
        const float sc0 = __expf(m0 - mn0);
        const float sc1 = __expf(m1 - mn1);
        m0 = mn0; m1 = mn1;

        float ls0 = 0.0f, ls1 = 0.0f;
#pragma unroll
        for (int nt = 0; nt < 16; nt++) {
            s[nt][0] = __expf(s[nt][0] - mn0);
            s[nt][1] = __expf(s[nt][1] - mn0);
            s[nt][2] = __expf(s[nt][2] - mn1);
            s[nt][3] = __expf(s[nt][3] - mn1);
            ls0 += s[nt][0] + s[nt][1];
            ls1 += s[nt][2] + s[nt][3];
        }
        ls0 += __shfl_xor_sync(0xffffffffu, ls0, 1);
        ls0 += __shfl_xor_sync(0xffffffffu, ls0, 2);
        ls1 += __shfl_xor_sync(0xffffffffu, ls1, 1);
        ls1 += __shfl_xor_sync(0xffffffffu, ls1, 2);
        l0 = l0 * sc0 + ls0;
        l1 = l1 * sc1 + ls1;

#pragma unroll
        for (int nt = 0; nt < 8; nt++) {
            o[nt][0] *= sc0; o[nt][1] *= sc0;
            o[nt][2] *= sc1; o[nt][3] *= sc1;
        }

        // ---- O += P @ V : P A-fragments repacked from S accumulators ----
#pragma unroll
        for (int ksv = 0; ksv < 8; ksv++) {
            const int nt0 = 2 * ksv, nt1 = 2 * ksv + 1;
            uint32_t ph[4], pl[4];
            ph[0] = pack_hi(s[nt0][0], s[nt0][1]);
            ph[1] = pack_hi(s[nt0][2], s[nt0][3]);
            ph[2] = pack_hi(s[nt1][0], s[nt1][1]);
            ph[3] = pack_hi(s[nt1][2], s[nt1][3]);
            pl[0] = pack_lo(s[nt0][0], s[nt0][1]);
            pl[1] = pack_lo(s[nt0][2], s[nt0][3]);
            pl[2] = pack_lo(s[nt1][0], s[nt1][1]);
            pl[3] = pack_lo(s[nt1][2], s[nt1][3]);
#pragma unroll
            for (int g = 0; g < 4; g++) {
                uint32_t vh[4], vl[4];
                const uint32_t vd = vBase + (uint32_t)(ksv * 16 * 144 + g * 32);
                ldm_x4t(vd, vh);
                ldm_x4t(vd + 18432, vl);
#pragma unroll
                for (int h2 = 0; h2 < 2; h2++) {
                    const int nt = g * 2 + h2;
                    mma16816(o[nt], ph, &vh[h2 * 2]);
                    mma16816(o[nt], pl, &vh[h2 * 2]);
                    mma16816(o[nt], ph, &vl[h2 * 2]);
                }
            }
        }
    }

    // ---- epilogue: normalize, write fp32 g_att ----
    const float inv0 = 1.0f / l0;
    const float inv1 = 1.0f / l1;
    const int grow0 = q0 + rloc0;
    const int grow1 = q0 + rloc1;
#pragma unroll
    for (int nt = 0; nt < 8; nt++) {
        const int d = nt * 8 + (lane & 3) * 2;
        float* dst0 = g_att + ((size_t)(b * T_SEQ + grow0)) * CEMB + h * HS + d;
        *(float2*)dst0 = make_float2(o[nt][0] * inv0, o[nt][1] * inv0);
        float* dst1 = g_att + ((size_t)(b * T_SEQ + grow1)) * CEMB + h * HS + d;
        *(float2*)dst1 = make_float2(o[nt][2] * inv1, o[nt][3] * inv1);
    }
}

// ============================================================================
// launch
// ============================================================================
extern "C" void kernel_launch(void* const* d_in, const int* in_sizes, int n_in,
                              void* d_out, int out_size)
{
    const float* x    = (const float*)d_in[0];
    const float* Wqkv = (const float*)d_in[1];
    const float* bqkv = (const float*)d_in[2];
    const float* Wo   = (const float*)d_in[3];
    const float* bo   = (const float*)d_in[4];
    float* out = (float*)d_out;

    cudaFuncSetAttribute(attn_mma, cudaFuncAttributeMaxDynamicSharedMemorySize, ATTN_SMEM);
    cudaFuncSetAttribute(mma_gemm<0>, cudaFuncAttributeMaxDynamicSharedMemorySize, GEMM_SMEM);
    cudaFuncSetAttribute(mma_gemm<1>, cudaFuncAttributeMaxDynamicSharedMemorySize, GEMM_SMEM);

    // 1) QKV projection -> g_q/g_k/g_v
    mma_gemm<0><<<dim3(C3 / 128, MTOT / 128), 256, GEMM_SMEM>>>(x, Wqkv, bqkv, nullptr, C3);

    // 2) causal flash attention (mma.sync bf16x3) -> g_att
    attn_mma<<<dim3(T_SEQ / 128, NH, NB), 256, ATTN_SMEM>>>();

    // 3) output projection -> d_out
    mma_gemm<1><<<dim3(CEMB / 128, MTOT / 128), 256, GEMM_SMEM>>>(nullptr, Wo, bo, out, CEMB);
}

// round 11
// speedup vs baseline: 2.9700x; 1.1245x over previous
#include <cuda_runtime.h>
#include <cuda_bf16.h>
#include <cstdint>

// ---------------- problem constants ----------------
#define T_SEQ 2048
#define NB    2
#define NH    16
#define HS    64
#define CEMB  1024
#define C3    3072
#define MTOT  (NB * T_SEQ)   // 4096

// ---------------- device scratch: 64 MiB total (proven-safe footprint) ----
__device__ float g_q[NB * NH * T_SEQ * HS];     // 16 MiB
__device__ float g_k[NB * NH * T_SEQ * HS];     // 16 MiB
__device__ float g_v[NB * NH * T_SEQ * HS];     // 16 MiB
__device__ float g_att[MTOT * CEMB];            // 16 MiB  [b*T+t][h*64+d]

// ============================================================================
// helpers
// ============================================================================
__device__ __forceinline__ uint32_t smem_u32(const void* p) {
    uint32_t a;
    asm("{ .reg .u64 t; cvta.to.shared.u64 t, %1; cvt.u32.u64 %0, t; }"
        : "=r"(a) : "l"(p));
    return a;
}
__device__ __forceinline__ void split2(float v, __nv_bfloat16& h, __nv_bfloat16& l) {
    h = __float2bfloat16(v);
    l = __float2bfloat16(v - __bfloat162float(h));
}
__device__ __forceinline__ uint32_t pack_hi(float a, float b) {
    __nv_bfloat162 t;
    t.x = __float2bfloat16(a);
    t.y = __float2bfloat16(b);
    return *(uint32_t*)&t;
}
__device__ __forceinline__ uint32_t pack_lo(float a, float b) {
    __nv_bfloat16 ha = __float2bfloat16(a);
    __nv_bfloat16 hb = __float2bfloat16(b);
    __nv_bfloat162 t;
    t.x = __float2bfloat16(a - __bfloat162float(ha));
    t.y = __float2bfloat16(b - __bfloat162float(hb));
    return *(uint32_t*)&t;
}

__device__ __forceinline__ void ldm_x4(uint32_t addr, uint32_t r[4]) {
    asm volatile("ldmatrix.sync.aligned.m8n8.x4.shared.b16 {%0,%1,%2,%3}, [%4];"
        : "=r"(r[0]), "=r"(r[1]), "=r"(r[2]), "=r"(r[3]) : "r"(addr));
}
__device__ __forceinline__ void ldm_x4t(uint32_t addr, uint32_t r[4]) {
    asm volatile("ldmatrix.sync.aligned.m8n8.x4.trans.shared.b16 {%0,%1,%2,%3}, [%4];"
        : "=r"(r[0]), "=r"(r[1]), "=r"(r[2]), "=r"(r[3]) : "r"(addr));
}
__device__ __forceinline__ void mma16816(float c[4], const uint32_t a[4],
                                         const uint32_t b[2]) {
    asm volatile(
        "mma.sync.aligned.m16n8k16.row.col.f32.bf16.bf16.f32 "
        "{%0,%1,%2,%3}, {%4,%5,%6,%7}, {%8,%9}, {%0,%1,%2,%3};"
        : "+f"(c[0]), "+f"(c[1]), "+f"(c[2]), "+f"(c[3])
        : "r"(a[0]), "r"(a[1]), "r"(a[2]), "r"(a[3]), "r"(b[0]), "r"(b[1]));
}

// ============================================================================
// warp-MMA bf16x3 GEMM, v2: CTA tile 128x64, BK=64, 8 warps (warp 32x32),
// __launch_bounds__(256, 2) -> <=128 regs -> 2 CTAs/SM so one CTA's fill
// phase overlaps the other's MMA phase (round-9 ncu: tensor=44.8%, occ=12.3%,
// fill serialized -> occupancy is the overlap mechanism).
// smem: A_hi/A_lo [128][72 bf16] s144 (18,432 B each),
//       B_hi/B_lo [64 k][64 n]   s144 ( 9,216 B each).  Total 55,296 B/CTA.
// MODE 0: A = x, scatter -> g_q/g_k/g_v (N = 3072)
// MODE 1: A = g_att, write Cout + bias  (N = 1024)
// ============================================================================
#define A_TILE  18432            // 128 * 144
#define B_TILE2  9216            // 64 * 144
#define GEMM_SMEM (2 * A_TILE + 2 * B_TILE2)   // 55,296 B

template <int MODE>
__global__ void __launch_bounds__(256, 2)
mma_gemm(const float* __restrict__ Aglob, const float* __restrict__ W,
         const float* __restrict__ bias, float* __restrict__ Cout, int N)
{
    extern __shared__ char smem[];
    const uint32_t sA_hi = smem_u32(smem);
    const uint32_t sB_hi = sA_hi + 2 * A_TILE;
    char* pA_hi = smem;
    char* pA_lo = smem + A_TILE;
    char* pB_hi = smem + 2 * A_TILE;
    char* pB_lo = pB_hi + B_TILE2;

    const int tid  = threadIdx.x;
    const int lane = tid & 31;
    const int wid  = tid >> 5;
    const int m0   = blockIdx.y * 128;
    const int n0   = blockIdx.x * 64;
    const int wm0  = (wid & 3) * 32;        // 4 warps over 128 M
    const int wn0  = (wid >> 2) * 32;       // 2 warps over 64 N

    const float* A = (MODE == 0) ? Aglob : (const float*)g_att;

    float acc[2][4][4];                     // 32 regs
#pragma unroll
    for (int mt = 0; mt < 2; mt++)
#pragma unroll
        for (int nt = 0; nt < 4; nt++)
#pragma unroll
            for (int e = 0; e < 4; e++) acc[mt][nt][e] = 0.0f;

    const int a_row  = lane & 15;
    const int a_cb   = (lane >> 4) * 16;
    const int b_krow = ((lane >> 3) & 1) * 8 + (lane & 7);
    const int b_nb   = (lane >> 4) * 16;

    const uint32_t aBase = sA_hi + (uint32_t)((wm0 + a_row) * 144 + a_cb);
    const uint32_t bBase = sB_hi + (uint32_t)(b_krow * 144 + wn0 * 2 + b_nb);

    constexpr int NKT = CEMB / 64;   // 16
    for (int kt = 0; kt < NKT; kt++) {
        __syncthreads();   // previous chunk's MMAs done reading smem

        // ---- fill A: 128 m x 64 k fp32 -> split bf16 (k-contiguous) ----
#pragma unroll
        for (int j = 0; j < 8; j++) {
            const int idx = tid + j * 256;        // 0..2047
            const int m = idx >> 4;
            const int c = idx & 15;
            float4 v = *(const float4*)(A + (size_t)(m0 + m) * CEMB + kt * 64 + c * 4);
            __nv_bfloat16 h0, h1, h2, h3, l0, l1, l2, l3;
            split2(v.x, h0, l0); split2(v.y, h1, l1);
            split2(v.z, h2, l2); split2(v.w, h3, l3);
            __nv_bfloat162 hA, hB, lA, lB;
            hA.x = h0; hA.y = h1; hB.x = h2; hB.y = h3;
            lA.x = l0; lA.y = l1; lB.x = l2; lB.y = l3;
            const int so = m * 144 + c * 8;
            *(__nv_bfloat162*)(pA_hi + so)     = hA;
            *(__nv_bfloat162*)(pA_hi + so + 4) = hB;
            *(__nv_bfloat162*)(pA_lo + so)     = lA;
            *(__nv_bfloat162*)(pA_lo + so + 4) = lB;
        }
        // ---- fill W: 64 k x 64 n fp32 -> split bf16 (n-contiguous) ----
#pragma unroll
        for (int j = 0; j < 4; j++) {
            const int idx = tid + j * 256;        // 0..1023
            const int k = idx >> 4;               // 0..63
            const int c = idx & 15;               // float4 within 64 n
            float4 v = *(const float4*)(W + (size_t)(kt * 64 + k) * N + n0 + c * 4);
            __nv_bfloat16 h0, h1, h2, h3, l0, l1, l2, l3;
            split2(v.x, h0, l0); split2(v.y, h1, l1);
            split2(v.z, h2, l2); split2(v.w, h3, l3);
            __nv_bfloat162 hA, hB, lA, lB;
            hA.x = h0; hA.y = h1; hB.x = h2; hB.y = h3;
            lA.x = l0; lA.y = l1; lB.x = l2; lB.y = l3;
            const int so = k * 144 + c * 8;
            *(__nv_bfloat162*)(pB_hi + so)     = hA;
            *(__nv_bfloat162*)(pB_hi + so + 4) = hB;
            *(__nv_bfloat162*)(pB_lo + so)     = lA;
            *(__nv_bfloat162*)(pB_lo + so + 4) = lB;
        }
        __syncthreads();

        // ---- MMA phase: 4 k-steps of 16 ----
#pragma unroll
        for (int ks = 0; ks < 4; ks++) {
            uint32_t bhi[2][4], blo[2][4];
#pragma unroll
            for (int g = 0; g < 2; g++) {
                const uint32_t bd = bBase + (uint32_t)(ks * 16 * 144 + g * 32);
                ldm_x4t(bd, bhi[g]);
                ldm_x4t(bd + B_TILE2, blo[g]);
            }
#pragma unroll
            for (int mt = 0; mt < 2; mt++) {
                uint32_t ahi[4], alo[4];
                const uint32_t ad = aBase + (uint32_t)(mt * 16 * 144 + ks * 32);
                ldm_x4(ad, ahi);
                ldm_x4(ad + A_TILE, alo);
#pragma unroll
                for (int g = 0; g < 2; g++)
#pragma unroll
                    for (int h2 = 0; h2 < 2; h2++) {
                        const int nt = g * 2 + h2;
                        mma16816(acc[mt][nt], ahi, &bhi[g][h2 * 2]);
                        mma16816(acc[mt][nt], alo, &bhi[g][h2 * 2]);
                        mma16816(acc[mt][nt], ahi, &blo[g][h2 * 2]);
                    }
            }
        }
    }

    // ---------------- epilogue ----------------
#pragma unroll
    for (int mt = 0; mt < 2; mt++) {
        const int mrow = m0 + wm0 + mt * 16 + (lane >> 2);
#pragma unroll
        for (int nt = 0; nt < 4; nt++) {
            const int nb = n0 + wn0 + nt * 8 + (lane & 3) * 2;
            const float b0 = bias[nb], b1 = bias[nb + 1];
            const float* a = acc[mt][nt];
            if (MODE == 0) {
                const int hh = nb / 192;
                const int e  = nb - hh * 192;
                const int wh = e >> 6;
                const int d0 = e & 63;
                float* arr = (wh == 0) ? g_q : (wh == 1) ? g_k : g_v;
                const int bi = mrow >> 11;
                const int t  = mrow & (T_SEQ - 1);
                float* dst0 = arr + ((size_t)((bi * NH + hh) * T_SEQ + t)) * HS + d0;
                *(float2*)dst0 = make_float2(a[0] + b0, a[1] + b1);
                float* dst1 = arr + ((size_t)((bi * NH + hh) * T_SEQ + t + 8)) * HS + d0;
                *(float2*)dst1 = make_float2(a[2] + b0, a[3] + b1);
            } else {
                float* dst0 = Cout + (size_t)mrow * N + nb;
                *(float2*)dst0 = make_float2(a[0] + b0, a[1] + b1);
                float* dst1 = Cout + (size_t)(mrow + 8) * N + nb;
                *(float2*)dst1 = make_float2(a[2] + b0, a[3] + b1);
            }
        }
    }
}

// ============================================================================
// Causal flash attention on mma.sync bf16x3 (BYTE-IDENTICAL to passing R9).
// ============================================================================
#define QOFF 0
#define KOFF (2 * 18432)
#define VOFF (4 * 18432)
#define ATTN_SMEM (6 * 18432)    // 110,592 B

__device__ __forceinline__ void fill_split_qkv(const float* __restrict__ src,
                                               char* __restrict__ hi,
                                               char* __restrict__ lo,
                                               int tid, float scl)
{
#pragma unroll
    for (int j = 0; j < 8; j++) {
        const int idx = tid + j * 256;
        const int m = idx >> 4;
        const int c = idx & 15;
        float4 v = *(const float4*)(src + (size_t)m * HS + c * 4);
        v.x *= scl; v.y *= scl; v.z *= scl; v.w *= scl;
        __nv_bfloat16 h0, h1, h2, h3, l0, l1, l2, l3;
        split2(v.x, h0, l0); split2(v.y, h1, l1);
        split2(v.z, h2, l2); split2(v.w, h3, l3);
        __nv_bfloat162 hA, hB, lA, lB;
        hA.x = h0; hA.y = h1; hB.x = h2; hB.y = h3;
        lA.x = l0; lA.y = l1; lB.x = l2; lB.y = l3;
        const int so = m * 144 + c * 8;
        *(__nv_bfloat162*)(hi + so)     = hA;
        *(__nv_bfloat162*)(hi + so + 4) = hB;
        *(__nv_bfloat162*)(lo + so)     = lA;
        *(__nv_bfloat162*)(lo + so + 4) = lB;
    }
}

__global__ void __launch_bounds__(256, 1)
attn_mma(void)
{
    extern __shared__ char smem[];
    const uint32_t sbase = smem_u32(smem);
    const int tid  = threadIdx.x;
    const int lane = tid & 31;
    const int wid  = tid >> 5;

    const int qt = gridDim.x - 1 - blockIdx.x;   // heavy q-tiles first
    const int h  = blockIdx.y;
    const int b  = blockIdx.z;
    const int q0 = qt * 128;

    const size_t base = (size_t)(b * NH + h) * T_SEQ * HS;
    const float* Qg = g_q + base + (size_t)q0 * HS;
    const float* Kg = g_k + base;
    const float* Vg = g_v + base;

    fill_split_qkv(Qg, smem + QOFF, smem + QOFF + 18432, tid, 0.125f);

    const uint32_t aBase = sbase + QOFF +
        (uint32_t)((wid * 16 + (lane & 15)) * 144 + (lane >> 4) * 16);
    const uint32_t kBase = sbase + KOFF +
        (uint32_t)(((((lane >> 4) << 3) + (lane & 7)) * 144) + ((lane >> 3) & 1) * 16);
    const uint32_t vBase = sbase + VOFF +
        (uint32_t)(((((lane >> 3) & 1) * 8 + (lane & 7)) * 144) + (lane >> 4) * 16);

    float o[8][4];
#pragma unroll
    for (int nt = 0; nt < 8; nt++)
#pragma unroll
        for (int e = 0; e < 4; e++) o[nt][e] = 0.0f;
    float m0 = -1e30f, m1 = -1e30f, l0 = 0.0f, l1 = 0.0f;

    const int rloc0 = wid * 16 + (lane >> 2);
    const int rloc1 = rloc0 + 8;

    for (int kt = 0; kt <= qt; kt++) {
        __syncthreads();
        fill_split_qkv(Kg + (size_t)(kt * 128) * HS,
                       smem + KOFF, smem + KOFF + 18432, tid, 1.0f);
        fill_split_qkv(Vg + (size_t)(kt * 128) * HS,
                       smem + VOFF, smem + VOFF + 18432, tid, 1.0f);
        __syncthreads();

        float s[16][4];
#pragma unroll
        for (int nt = 0; nt < 16; nt++)
#pragma unroll
            for (int e = 0; e < 4; e++) s[nt][e] = 0.0f;

#pragma unroll
        for (int ks = 0; ks < 4; ks++) {
            uint32_t ahi[4], alo[4];
            ldm_x4(aBase + ks * 32, ahi);
            ldm_x4(aBase + 18432 + ks * 32, alo);
#pragma unroll
            for (int g = 0; g < 8; g++) {
                uint32_t kh[4], kl[4];
                const uint32_t kd = kBase + (uint32_t)(g * 16 * 144 + ks * 32);
                ldm_x4(kd, kh);
                ldm_x4(kd + 18432, kl);
#pragma unroll
                for (int h2 = 0; h2 < 2; h2++) {
                    const int nt = g * 2 + h2;
                    mma16816(s[nt], ahi, &kh[h2 * 2]);
                    mma16816(s[nt], alo, &kh[h2 * 2]);
                    mma16816(s[nt], ahi, &kl[h2 * 2]);
                }
            }
        }

        if (kt == qt) {
#pragma unroll
            for (int nt = 0; nt < 16; nt++) {
                const int c0 = nt * 8 + (lane & 3) * 2;
                const int c1 = c0 + 1;
                if (c0 > rloc0) s[nt][0] = -1e30f;
                if (c1 > rloc0) s[nt][1] = -1e30f;
                if (c0 > rloc1) s[nt][2] = -1e30f;
                if (c1 > rloc1) s[nt][3] = -1e30f;
            }
        }

        float mx0 = -1e30f, mx1 = -1e30f;
#pragma unroll
        for (int nt = 0; nt < 16; nt++) {
            mx0 = fmaxf(mx0, fmaxf(s[nt][0], s[nt][1]));
            mx1 = fmaxf(mx1, fmaxf(s[nt][2], s[nt][3]));
        }
        mx0 = fmaxf(mx0, __shfl_xor_sync(0xffffffffu, mx0, 1));
        mx0 = fmaxf(mx0, __shfl_xor_sync(0xffffffffu, mx0, 2));
        mx1 = fmaxf(mx1, __shfl_xor_sync(0xffffffffu, mx1, 1));
        mx1 = fmaxf(mx1, __shfl_xor_sync(0xffffffffu, mx1, 2));

        const float mn0 = fmaxf(m0, mx0);
        const float mn1 = fmaxf(m1, mx1);
        const float sc0 = __expf(m0 - mn0);
        const float sc1 = __expf(m1 - mn1);
        m0 = mn0; m1 = mn1;

        float ls0 = 0.0f, ls1 = 0.0f;
#pragma unroll
        for (int nt = 0; nt < 16; nt++) {
            s[nt][0] = __expf(s[nt][0] - mn0);
            s[nt][1] = __expf(s[nt][1] - mn0);
            s[nt][2] = __expf(s[nt][2] - mn1);
            s[nt][3] = __expf(s[nt][3] - mn1);
            ls0 += s[nt][0] + s[nt][1];
            ls1 += s[nt][2] + s[nt][3];
        }
        ls0 += __shfl_xor_sync(0xffffffffu, ls0, 1);
        ls0 += __shfl_xor_sync(0xffffffffu, ls0, 2);
        ls1 += __shfl_xor_sync(0xffffffffu, ls1, 1);
        ls1 += __shfl_xor_sync(0xffffffffu, ls1, 2);
        l0 = l0 * sc0 + ls0;
        l1 = l1 * sc1 + ls1;

#pragma unroll
        for (int nt = 0; nt < 8; nt++) {
            o[nt][0] *= sc0; o[nt][1] *= sc0;
            o[nt][2] *= sc1; o[nt][3] *= sc1;
        }

#pragma unroll
        for (int ksv = 0; ksv < 8; ksv++) {
            const int nt0 = 2 * ksv, nt1 = 2 * ksv + 1;
            uint32_t ph[4], pl[4];
            ph[0] = pack_hi(s[nt0][0], s[nt0][1]);
            ph[1] = pack_hi(s[nt0][2], s[nt0][3]);
            ph[2] = pack_hi(s[nt1][0], s[nt1][1]);
            ph[3] = pack_hi(s[nt1][2], s[nt1][3]);
            pl[0] = pack_lo(s[nt0][0], s[nt0][1]);
            pl[1] = pack_lo(s[nt0][2], s[nt0][3]);
            pl[2] = pack_lo(s[nt1][0], s[nt1][1]);
            pl[3] = pack_lo(s[nt1][2], s[nt1][3]);
#pragma unroll
            for (int g = 0; g < 4; g++) {
                uint32_t vh[4], vl[4];
                const uint32_t vd = vBase + (uint32_t)(ksv * 16 * 144 + g * 32);
                ldm_x4t(vd, vh);
                ldm_x4t(vd + 18432, vl);
#pragma unroll
                for (int h2 = 0; h2 < 2; h2++) {
                    const int nt = g * 2 + h2;
                    mma16816(o[nt], ph, &vh[h2 * 2]);
                    mma16816(o[nt], pl, &vh[h2 * 2]);
                    mma16816(o[nt], ph, &vl[h2 * 2]);
                }
            }
        }
    }

    const float inv0 = 1.0f / l0;
    const float inv1 = 1.0f / l1;
    const int grow0 = q0 + rloc0;
    const int grow1 = q0 + rloc1;
#pragma unroll
    for (int nt = 0; nt < 8; nt++) {
        const int d = nt * 8 + (lane & 3) * 2;
        float* dst0 = g_att + ((size_t)(b * T_SEQ + grow0)) * CEMB + h * HS + d;
        *(float2*)dst0 = make_float2(o[nt][0] * inv0, o[nt][1] * inv0);
        float* dst1 = g_att + ((size_t)(b * T_SEQ + grow1)) * CEMB + h * HS + d;
        *(float2*)dst1 = make_float2(o[nt][2] * inv1, o[nt][3] * inv1);
    }
}

// ============================================================================
// launch
// ============================================================================
extern "C" void kernel_launch(void* const* d_in, const int* in_sizes, int n_in,
                              void* d_out, int out_size)
{
    const float* x    = (const float*)d_in[0];
    const float* Wqkv = (const float*)d_in[1];
    const float* bqkv = (const float*)d_in[2];
    const float* Wo   = (const float*)d_in[3];
    const float* bo   = (const float*)d_in[4];
    float* out = (float*)d_out;

    cudaFuncSetAttribute(attn_mma, cudaFuncAttributeMaxDynamicSharedMemorySize, ATTN_SMEM);
    cudaFuncSetAttribute(mma_gemm<0>, cudaFuncAttributeMaxDynamicSharedMemorySize, GEMM_SMEM);
    cudaFuncSetAttribute(mma_gemm<1>, cudaFuncAttributeMaxDynamicSharedMemorySize, GEMM_SMEM);

    // 1) QKV projection -> g_q/g_k/g_v   (N tiles of 64)
    mma_gemm<0><<<dim3(C3 / 64, MTOT / 128), 256, GEMM_SMEM>>>(x, Wqkv, bqkv, nullptr, C3);

    // 2) causal flash attention (mma.sync bf16x3) -> g_att
    attn_mma<<<dim3(T_SEQ / 128, NH, NB), 256, ATTN_SMEM>>>();

    // 3) output projection -> d_out
    mma_gemm<1><<<dim3(CEMB / 64, MTOT / 128), 256, GEMM_SMEM>>>(nullptr, Wo, bo, out, CEMB);
}

// round 12
// speedup vs baseline: 3.0432x; 1.0247x over previous
#include <cuda_runtime.h>
#include <cuda_bf16.h>
#include <cstdint>

// ---------------- problem constants ----------------
#define T_SEQ 2048
#define NB    2
#define NH    16
#define HS    64
#define CEMB  1024
#define C3    3072
#define MTOT  (NB * T_SEQ)            // 4096
#define NQKV  (NB * NH * T_SEQ * HS)  // 4,194,304

// ---------------- device scratch: 64 MiB total (proven-safe footprint) ----
// split-bf16 planes: hi + lo = 4 B/elem, same as the fp32 arrays they replace
__device__ __align__(16) __nv_bfloat16 g_q_hi[NQKV];
__device__ __align__(16) __nv_bfloat16 g_q_lo[NQKV];
__device__ __align__(16) __nv_bfloat16 g_k_hi[NQKV];
__device__ __align__(16) __nv_bfloat16 g_k_lo[NQKV];
__device__ __align__(16) __nv_bfloat16 g_v_hi[NQKV];
__device__ __align__(16) __nv_bfloat16 g_v_lo[NQKV];
// aliased buffer: holds split-x during gemm0, attention output after attn
__device__ __align__(16) __nv_bfloat16 g_a_hi[MTOT * CEMB];
__device__ __align__(16) __nv_bfloat16 g_a_lo[MTOT * CEMB];

// ============================================================================
// helpers
// ============================================================================
__device__ __forceinline__ uint32_t smem_u32(const void* p) {
    uint32_t a;
    asm("{ .reg .u64 t; cvta.to.shared.u64 t, %1; cvt.u32.u64 %0, t; }"
        : "=r"(a) : "l"(p));
    return a;
}
__device__ __forceinline__ void split2(float v, __nv_bfloat16& h, __nv_bfloat16& l) {
    h = __float2bfloat16(v);
    l = __float2bfloat16(v - __bfloat162float(h));
}
__device__ __forceinline__ uint32_t pack_hi(float a, float b) {
    __nv_bfloat162 t;
    t.x = __float2bfloat16(a);
    t.y = __float2bfloat16(b);
    return *(uint32_t*)&t;
}
__device__ __forceinline__ uint32_t pack_lo(float a, float b) {
    __nv_bfloat16 ha = __float2bfloat16(a);
    __nv_bfloat16 hb = __float2bfloat16(b);
    __nv_bfloat162 t;
    t.x = __float2bfloat16(a - __bfloat162float(ha));
    t.y = __float2bfloat16(b - __bfloat162float(hb));
    return *(uint32_t*)&t;
}
__device__ __forceinline__ void cp16(uint32_t d, const void* s) {
    asm volatile("cp.async.cg.shared.global [%0], [%1], 16;" :: "r"(d), "l"(s));
}
#define CP_COMMIT() asm volatile("cp.async.commit_group;" ::: "memory")
#define CP_WAIT1()  asm volatile("cp.async.wait_group 1;" ::: "memory")
#define CP_WAIT0()  asm volatile("cp.async.wait_group 0;" ::: "memory")

__device__ __forceinline__ void ldm_x4(uint32_t addr, uint32_t r[4]) {
    asm volatile("ldmatrix.sync.aligned.m8n8.x4.shared.b16 {%0,%1,%2,%3}, [%4];"
        : "=r"(r[0]), "=r"(r[1]), "=r"(r[2]), "=r"(r[3]) : "r"(addr));
}
__device__ __forceinline__ void ldm_x4t(uint32_t addr, uint32_t r[4]) {
    asm volatile("ldmatrix.sync.aligned.m8n8.x4.trans.shared.b16 {%0,%1,%2,%3}, [%4];"
        : "=r"(r[0]), "=r"(r[1]), "=r"(r[2]), "=r"(r[3]) : "r"(addr));
}
__device__ __forceinline__ void mma16816(float c[4], const uint32_t a[4],
                                         const uint32_t b[2]) {
    asm volatile(
        "mma.sync.aligned.m16n8k16.row.col.f32.bf16.bf16.f32 "
        "{%0,%1,%2,%3}, {%4,%5,%6,%7}, {%8,%9}, {%0,%1,%2,%3};"
        : "+f"(c[0]), "+f"(c[1]), "+f"(c[2]), "+f"(c[3])
        : "r"(a[0]), "r"(a[1]), "r"(a[2]), "r"(a[3]), "r"(b[0]), "r"(b[1]));
}

// ============================================================================
// x [4096][1024] fp32 -> g_a_hi / g_a_lo (split once; gemm0 reads from here)
// ============================================================================
__global__ void __launch_bounds__(256) k_split_x(const float4* __restrict__ x) {
    int i = blockIdx.x * 256 + threadIdx.x;
    float4 v = x[i];
    __nv_bfloat16 h0, h1, h2, h3, l0, l1, l2, l3;
    split2(v.x, h0, l0); split2(v.y, h1, l1);
    split2(v.z, h2, l2); split2(v.w, h3, l3);
    __nv_bfloat162 a, b, c, d;
    a.x = h0; a.y = h1; b.x = h2; b.y = h3;
    c.x = l0; c.y = l1; d.x = l2; d.y = l3;
    ((__nv_bfloat162*)g_a_hi)[2 * i]     = a;
    ((__nv_bfloat162*)g_a_hi)[2 * i + 1] = b;
    ((__nv_bfloat162*)g_a_lo)[2 * i]     = c;
    ((__nv_bfloat162*)g_a_lo)[2 * i + 1] = d;
}

// ============================================================================
// warp-MMA bf16x3 GEMM v3: CTA 128x64, BK=64, 8 warps, 2 CTAs/SM.
// A comes pre-split from g_a planes via cp.async (overlaps W inline split).
// MODE 0: scatter split-bf16 -> g_q/g_k/g_v planes (N=3072)
// MODE 1: write Cout fp32 + bias (N=1024)
// ============================================================================
#define A_TILE  18432            // 128 * 144
#define B_TILE2  9216            // 64 * 144
#define GEMM_SMEM (2 * A_TILE + 2 * B_TILE2)   // 55,296 B

template <int MODE>
__global__ void __launch_bounds__(256, 2)
mma_gemm(const float* __restrict__ W, const float* __restrict__ bias,
         float* __restrict__ Cout, int N)
{
    extern __shared__ char smem[];
    const uint32_t sbase = smem_u32(smem);
    const uint32_t sA_hi = sbase;
    const uint32_t sA_lo = sbase + A_TILE;
    const uint32_t sB_hi = sbase + 2 * A_TILE;
    char* pB_hi = smem + 2 * A_TILE;
    char* pB_lo = pB_hi + B_TILE2;

    const int tid  = threadIdx.x;
    const int lane = tid & 31;
    const int wid  = tid >> 5;
    const int m0   = blockIdx.y * 128;
    const int n0   = blockIdx.x * 64;
    const int wm0  = (wid & 3) * 32;
    const int wn0  = (wid >> 2) * 32;

    float acc[2][4][4];
#pragma unroll
    for (int mt = 0; mt < 2; mt++)
#pragma unroll
        for (int nt = 0; nt < 4; nt++)
#pragma unroll
            for (int e = 0; e < 4; e++) acc[mt][nt][e] = 0.0f;

    const int a_row  = lane & 15;
    const int a_cb   = (lane >> 4) * 16;
    const int b_krow = ((lane >> 3) & 1) * 8 + (lane & 7);
    const int b_nb   = (lane >> 4) * 16;

    const uint32_t aBase = sA_hi + (uint32_t)((wm0 + a_row) * 144 + a_cb);
    const uint32_t bBase = sB_hi + (uint32_t)(b_krow * 144 + wn0 * 2 + b_nb);

    constexpr int NKT = CEMB / 64;   // 16
    for (int kt = 0; kt < NKT; kt++) {
        __syncthreads();   // previous chunk's MMAs done reading smem
        const int ko = kt * 64;

        // ---- A: pure cp.async copy from pre-split planes ----
#pragma unroll
        for (int j = 0; j < 4; j++) {
            const int idx = tid + j * 256;      // 0..1023
            const int r = idx >> 3;
            const int c = idx & 7;
            const size_t go = (size_t)(m0 + r) * CEMB + ko + c * 8;
            const uint32_t so = (uint32_t)(r * 144 + c * 16);
            cp16(sA_hi + so, g_a_hi + go);
            cp16(sA_lo + so, g_a_lo + go);
        }
        CP_COMMIT();

        // ---- W: inline split (overlaps the A cp.async) ----
#pragma unroll
        for (int j = 0; j < 4; j++) {
            const int idx = tid + j * 256;
            const int k = idx >> 4;
            const int c = idx & 15;
            float4 v = *(const float4*)(W + (size_t)(ko + k) * N + n0 + c * 4);
            __nv_bfloat16 h0, h1, h2, h3, l0, l1, l2, l3;
            split2(v.x, h0, l0); split2(v.y, h1, l1);
            split2(v.z, h2, l2); split2(v.w, h3, l3);
            __nv_bfloat162 hA, hB, lA, lB;
            hA.x = h0; hA.y = h1; hB.x = h2; hB.y = h3;
            lA.x = l0; lA.y = l1; lB.x = l2; lB.y = l3;
            const int so = k * 144 + c * 8;
            *(__nv_bfloat162*)(pB_hi + so)     = hA;
            *(__nv_bfloat162*)(pB_hi + so + 4) = hB;
            *(__nv_bfloat162*)(pB_lo + so)     = lA;
            *(__nv_bfloat162*)(pB_lo + so + 4) = lB;
        }
        CP_WAIT0();
        __syncthreads();

        // ---- MMA phase ----
#pragma unroll
        for (int ks = 0; ks < 4; ks++) {
            uint32_t bhi[2][4], blo[2][4];
#pragma unroll
            for (int g = 0; g < 2; g++) {
                const uint32_t bd = bBase + (uint32_t)(ks * 16 * 144 + g * 32);
                ldm_x4t(bd, bhi[g]);
                ldm_x4t(bd + B_TILE2, blo[g]);
            }
#pragma unroll
            for (int mt = 0; mt < 2; mt++) {
                uint32_t ahi[4], alo[4];
                const uint32_t ad = aBase + (uint32_t)(mt * 16 * 144 + ks * 32);
                ldm_x4(ad, ahi);
                ldm_x4(ad + A_TILE, alo);
#pragma unroll
                for (int g = 0; g < 2; g++)
#pragma unroll
                    for (int h2 = 0; h2 < 2; h2++) {
                        const int nt = g * 2 + h2;
                        mma16816(acc[mt][nt], ahi, &bhi[g][h2 * 2]);
                        mma16816(acc[mt][nt], alo, &bhi[g][h2 * 2]);
                        mma16816(acc[mt][nt], ahi, &blo[g][h2 * 2]);
                    }
            }
        }
    }

    // ---------------- epilogue ----------------
#pragma unroll
    for (int mt = 0; mt < 2; mt++) {
        const int mrow = m0 + wm0 + mt * 16 + (lane >> 2);
#pragma unroll
        for (int nt = 0; nt < 4; nt++) {
            const int nb = n0 + wn0 + nt * 8 + (lane & 3) * 2;
            const float b0 = bias[nb], b1 = bias[nb + 1];
            const float* a = acc[mt][nt];
            if (MODE == 0) {
                const int hh = nb / 192;
                const int e  = nb - hh * 192;
                const int wh = e >> 6;
                const int d0 = e & 63;
                __nv_bfloat16* ah = (wh == 0) ? g_q_hi : (wh == 1) ? g_k_hi : g_v_hi;
                __nv_bfloat16* al = (wh == 0) ? g_q_lo : (wh == 1) ? g_k_lo : g_v_lo;
                const int bi = mrow >> 11;
                const int t  = mrow & (T_SEQ - 1);
                const size_t o0 = ((size_t)((bi * NH + hh) * T_SEQ + t)) * HS + d0;
                *(uint32_t*)(ah + o0) = pack_hi(a[0] + b0, a[1] + b1);
                *(uint32_t*)(al + o0) = pack_lo(a[0] + b0, a[1] + b1);
                const size_t o1 = o0 + (size_t)8 * HS;
                *(uint32_t*)(ah + o1) = pack_hi(a[2] + b0, a[3] + b1);
                *(uint32_t*)(al + o1) = pack_lo(a[2] + b0, a[3] + b1);
            } else {
                float* dst0 = Cout + (size_t)mrow * N + nb;
                *(float2*)dst0 = make_float2(a[0] + b0, a[1] + b1);
                float* dst1 = Cout + (size_t)(mrow + 8) * N + nb;
                *(float2*)dst1 = make_float2(a[2] + b0, a[3] + b1);
            }
        }
    }
}

// ============================================================================
// Causal flash attention, mma.sync bf16x3 with cp.async double-buffered K/V.
// smem: Q hi/lo (2x18432) + 2 KV buffers (K_hi,K_lo,V_hi,V_lo = 4x18432 each)
//     = 184,320 B.  Scale 1/8 applied to S after the QK^T MMA.
// Output written as split bf16 into g_a planes (gemm1 reads them directly).
// ============================================================================
#define KVBUF (4 * 18432)
#define ATTN_SMEM (2 * 18432 + 2 * KVBUF)   // 184,320 B

__device__ __forceinline__ void issue_kv(uint32_t kvb, size_t go_base, int tid) {
#pragma unroll
    for (int j = 0; j < 4; j++) {
        const int idx = tid + j * 256;
        const int r = idx >> 3;
        const int c = idx & 7;
        const size_t go = go_base + (size_t)r * HS + c * 8;
        const uint32_t so = (uint32_t)(r * 144 + c * 16);
        cp16(kvb + 0 * 18432 + so, g_k_hi + go);
        cp16(kvb + 1 * 18432 + so, g_k_lo + go);
        cp16(kvb + 2 * 18432 + so, g_v_hi + go);
        cp16(kvb + 3 * 18432 + so, g_v_lo + go);
    }
}

__global__ void __launch_bounds__(256, 1)
attn_mma(void)
{
    extern __shared__ char smem[];
    const uint32_t sbase = smem_u32(smem);
    const int tid  = threadIdx.x;
    const int lane = tid & 31;
    const int wid  = tid >> 5;

    const int qt = gridDim.x - 1 - blockIdx.x;   // heavy q-tiles first
    const int h  = blockIdx.y;
    const int b  = blockIdx.z;
    const int q0 = qt * 128;

    const size_t base = (size_t)(b * NH + h) * T_SEQ * HS;
    const size_t qbase = base + (size_t)q0 * HS;

    // ---- Q fill (cp.async, both planes) + first KV buffer ----
#pragma unroll
    for (int j = 0; j < 4; j++) {
        const int idx = tid + j * 256;
        const int r = idx >> 3;
        const int c = idx & 7;
        const size_t go = qbase + (size_t)r * HS + c * 8;
        const uint32_t so = (uint32_t)(r * 144 + c * 16);
        cp16(sbase + so, g_q_hi + go);
        cp16(sbase + 18432 + so, g_q_lo + go);
    }
    issue_kv(sbase + 2 * 18432, base, tid);
    CP_COMMIT();

    const uint32_t a_off = (uint32_t)((wid * 16 + (lane & 15)) * 144 + (lane >> 4) * 16);
    const uint32_t k_off = (uint32_t)(((((lane >> 4) << 3) + (lane & 7)) * 144) +
                                      ((lane >> 3) & 1) * 16);
    const uint32_t v_off = (uint32_t)(((((lane >> 3) & 1) * 8 + (lane & 7)) * 144) +
                                      (lane >> 4) * 16);
    const uint32_t aBase = sbase + a_off;

    float o[8][4];
#pragma unroll
    for (int nt = 0; nt < 8; nt++)
#pragma unroll
        for (int e = 0; e < 4; e++) o[nt][e] = 0.0f;
    float m0 = -1e30f, m1 = -1e30f, l0 = 0.0f, l1 = 0.0f;

    const int rloc0 = wid * 16 + (lane >> 2);
    const int rloc1 = rloc0 + 8;

    for (int kt = 0; kt <= qt; kt++) {
        const uint32_t kvb = sbase + 2 * 18432 + (uint32_t)(kt & 1) * KVBUF;
        if (kt < qt) {
            issue_kv(sbase + 2 * 18432 + (uint32_t)((kt + 1) & 1) * KVBUF,
                     base + (size_t)(kt + 1) * 128 * HS, tid);
            CP_COMMIT();
            CP_WAIT1();
        } else {
            CP_WAIT0();
        }
        __syncthreads();

        const uint32_t kBase = kvb + k_off;
        const uint32_t vBase = kvb + 2 * 18432 + v_off;

        // ---- S = Q @ K^T ----
        float s[16][4];
#pragma unroll
        for (int nt = 0; nt < 16; nt++)
#pragma unroll
            for (int e = 0; e < 4; e++) s[nt][e] = 0.0f;

#pragma unroll
        for (int ks = 0; ks < 4; ks++) {
            uint32_t ahi[4], alo[4];
            ldm_x4(aBase + ks * 32, ahi);
            ldm_x4(aBase + 18432 + ks * 32, alo);
#pragma unroll
            for (int g = 0; g < 8; g++) {
                uint32_t kh[4], kl[4];
                const uint32_t kd = kBase + (uint32_t)(g * 16 * 144 + ks * 32);
                ldm_x4(kd, kh);
                ldm_x4(kd + 18432, kl);
#pragma unroll
                for (int h2 = 0; h2 < 2; h2++) {
                    const int nt = g * 2 + h2;
                    mma16816(s[nt], ahi, &kh[h2 * 2]);
                    mma16816(s[nt], alo, &kh[h2 * 2]);
                    mma16816(s[nt], ahi, &kl[h2 * 2]);
                }
            }
        }

        // ---- scale by 1/sqrt(64), causal mask ----
#pragma unroll
        for (int nt = 0; nt < 16; nt++)
#pragma unroll
            for (int e = 0; e < 4; e++) s[nt][e] *= 0.125f;

        if (kt == qt) {
#pragma unroll
            for (int nt = 0; nt < 16; nt++) {
                const int c0 = nt * 8 + (lane & 3) * 2;
                const int c1 = c0 + 1;
                if (c0 > rloc0) s[nt][0] = -1e30f;
                if (c1 > rloc0) s[nt][1] = -1e30f;
                if (c0 > rloc1) s[nt][2] = -1e30f;
                if (c1 > rloc1) s[nt][3] = -1e30f;
            }
        }

        // ---- online softmax ----
        float mx0 = -1e30f, mx1 = -1e30f;
#pragma unroll
        for (int nt = 0; nt < 16; nt++) {
            mx0 = fmaxf(mx0, fmaxf(s[nt][0], s[nt][1]));
            mx1 = fmaxf(mx1, fmaxf(s[nt][2], s[nt][3]));
        }
        mx0 = fmaxf(mx0, __shfl_xor_sync(0xffffffffu, mx0, 1));
        mx0 = fmaxf(mx0, __shfl_xor_sync(0xffffffffu, mx0, 2));
        mx1 = fmaxf(mx1, __shfl_xor_sync(0xffffffffu, mx1, 1));
        mx1 = fmaxf(mx1, __shfl_xor_sync(0xffffffffu, mx1, 2));

        const float mn0 = fmaxf(m0, mx0);
        const float mn1 = fmaxf(m1, mx1);
        const float sc0 = __expf(m0 - mn0);
        const float sc1 = __expf(m1 - mn1);
        m0 = mn0; m1 = mn1;

        float ls0 = 0.0f, ls1 = 0.0f;
#pragma unroll
        for (int nt = 0; nt < 16; nt++) {
            s[nt][0] = __expf(s[nt][0] - mn0);
            s[nt][1] = __expf(s[nt][1] - mn0);
            s[nt][2] = __expf(s[nt][2] - mn1);
            s[nt][3] = __expf(s[nt][3] - mn1);
            ls0 += s[nt][0] + s[nt][1];
            ls1 += s[nt][2] + s[nt][3];
        }
        ls0 += __shfl_xor_sync(0xffffffffu, ls0, 1);
        ls0 += __shfl_xor_sync(0xffffffffu, ls0, 2);
        ls1 += __shfl_xor_sync(0xffffffffu, ls1, 1);
        ls1 += __shfl_xor_sync(0xffffffffu, ls1, 2);
        l0 = l0 * sc0 + ls0;
        l1 = l1 * sc1 + ls1;

#pragma unroll
        for (int nt = 0; nt < 8; nt++) {
            o[nt][0] *= sc0; o[nt][1] *= sc0;
            o[nt][2] *= sc1; o[nt][3] *= sc1;
        }

        // ---- O += P @ V ----
#pragma unroll
        for (int ksv = 0; ksv < 8; ksv++) {
            const int nt0 = 2 * ksv, nt1 = 2 * ksv + 1;
            uint32_t ph[4], pl[4];
            ph[0] = pack_hi(s[nt0][0], s[nt0][1]);
            ph[1] = pack_hi(s[nt0][2], s[nt0][3]);
            ph[2] = pack_hi(s[nt1][0], s[nt1][1]);
            ph[3] = pack_hi(s[nt1][2], s[nt1][3]);
            pl[0] = pack_lo(s[nt0][0], s[nt0][1]);
            pl[1] = pack_lo(s[nt0][2], s[nt0][3]);
            pl[2] = pack_lo(s[nt1][0], s[nt1][1]);
            pl[3] = pack_lo(s[nt1][2], s[nt1][3]);
#pragma unroll
            for (int g = 0; g < 4; g++) {
                uint32_t vh[4], vl[4];
                const uint32_t vd = vBase + (uint32_t)(ksv * 16 * 144 + g * 32);
                ldm_x4t(vd, vh);
                ldm_x4t(vd + 18432, vl);
#pragma unroll
                for (int h2 = 0; h2 < 2; h2++) {
                    const int nt = g * 2 + h2;
                    mma16816(o[nt], ph, &vh[h2 * 2]);
                    mma16816(o[nt], pl, &vh[h2 * 2]);
                    mma16816(o[nt], ph, &vl[h2 * 2]);
                }
            }
        }
        __syncthreads();   // all reads of this KV buffer done before overwrite
    }

    // ---- epilogue: normalize, write split bf16 to g_a planes ----
    const float inv0 = 1.0f / l0;
    const float inv1 = 1.0f / l1;
    const int grow0 = q0 + rloc0;
    const int grow1 = q0 + rloc1;
#pragma unroll
    for (int nt = 0; nt < 8; nt++) {
        const int d = nt * 8 + (lane & 3) * 2;
        const size_t o0 = ((size_t)(b * T_SEQ + grow0)) * CEMB + h * HS + d;
        *(uint32_t*)(g_a_hi + o0) = pack_hi(o[nt][0] * inv0, o[nt][1] * inv0);
        *(uint32_t*)(g_a_lo + o0) = pack_lo(o[nt][0] * inv0, o[nt][1] * inv0);
        const size_t o1 = ((size_t)(b * T_SEQ + grow1)) * CEMB + h * HS + d;
        *(uint32_t*)(g_a_hi + o1) = pack_hi(o[nt][2] * inv1, o[nt][3] * inv1);
        *(uint32_t*)(g_a_lo + o1) = pack_lo(o[nt][2] * inv1, o[nt][3] * inv1);
    }
}

// ============================================================================
// launch
// ============================================================================
extern "C" void kernel_launch(void* const* d_in, const int* in_sizes, int n_in,
                              void* d_out, int out_size)
{
    const float* x    = (const float*)d_in[0];
    const float* Wqkv = (const float*)d_in[1];
    const float* bqkv = (const float*)d_in[2];
    const float* Wo   = (const float*)d_in[3];
    const float* bo   = (const float*)d_in[4];
    float* out = (float*)d_out;

    cudaFuncSetAttribute(attn_mma, cudaFuncAttributeMaxDynamicSharedMemorySize, ATTN_SMEM);
    cudaFuncSetAttribute(mma_gemm<0>, cudaFuncAttributeMaxDynamicSharedMemorySize, GEMM_SMEM);
    cudaFuncSetAttribute(mma_gemm<1>, cudaFuncAttributeMaxDynamicSharedMemorySize, GEMM_SMEM);

    // 0) split x once -> g_a planes
    k_split_x<<<(MTOT * CEMB / 4) / 256, 256>>>((const float4*)x);

    // 1) QKV projection -> split g_q/g_k/g_v planes
    mma_gemm<0><<<dim3(C3 / 64, MTOT / 128), 256, GEMM_SMEM>>>(Wqkv, bqkv, nullptr, C3);

    // 2) causal flash attention -> split g_a planes
    attn_mma<<<dim3(T_SEQ / 128, NH, NB), 256, ATTN_SMEM>>>();

    // 3) output projection -> d_out (fp32 + bias)
    mma_gemm<1><<<dim3(CEMB / 64, MTOT / 128), 256, GEMM_SMEM>>>(Wo, bo, out, CEMB);
}

// round 14
// speedup vs baseline: 3.0561x; 1.0042x over previous
#include <cuda_runtime.h>
#include <cuda_bf16.h>
#include <cstdint>

// ---------------- problem constants ----------------
#define T_SEQ 2048
#define NB    2
#define NH    16
#define HS    64
#define CEMB  1024
#define C3    3072
#define MTOT  (NB * T_SEQ)            // 4096
#define NQKV  (NB * NH * T_SEQ * HS)  // 4,194,304

// ---------------- device scratch: EXACTLY 64 MiB (proven-safe budget) -----
__device__ __align__(16) __nv_bfloat16 g_q_hi[NQKV];   // also W2_hi scratch post-attn
__device__ __align__(16) __nv_bfloat16 g_q_lo[NQKV];   // also W2_lo scratch post-attn
__device__ __align__(16) __nv_bfloat16 g_k_hi[NQKV];
__device__ __align__(16) __nv_bfloat16 g_k_lo[NQKV];
__device__ __align__(16) __nv_bfloat16 g_v_hi[NQKV];
__device__ __align__(16) __nv_bfloat16 g_v_lo[NQKV];
// aliased: split-x during gemm0, attention output for gemm1
__device__ __align__(16) __nv_bfloat16 g_a_hi[MTOT * CEMB];
__device__ __align__(16) __nv_bfloat16 g_a_lo[MTOT * CEMB];
// W1 planes live in d_out (16 MiB harness buffer, dead until gemm1 epilogue).

// ============================================================================
// helpers
// ============================================================================
__device__ __forceinline__ uint32_t smem_u32(const void* p) {
    uint32_t a;
    asm("{ .reg .u64 t; cvta.to.shared.u64 t, %1; cvt.u32.u64 %0, t; }"
        : "=r"(a) : "l"(p));
    return a;
}
__device__ __forceinline__ void split2(float v, __nv_bfloat16& h, __nv_bfloat16& l) {
    h = __float2bfloat16(v);
    l = __float2bfloat16(v - __bfloat162float(h));
}
__device__ __forceinline__ uint32_t pack_hi(float a, float b) {
    __nv_bfloat162 t;
    t.x = __float2bfloat16(a);
    t.y = __float2bfloat16(b);
    return *(uint32_t*)&t;
}
__device__ __forceinline__ uint32_t pack_lo(float a, float b) {
    __nv_bfloat16 ha = __float2bfloat16(a);
    __nv_bfloat16 hb = __float2bfloat16(b);
    __nv_bfloat162 t;
    t.x = __float2bfloat16(a - __bfloat162float(ha));
    t.y = __float2bfloat16(b - __bfloat162float(hb));
    return *(uint32_t*)&t;
}
__device__ __forceinline__ void cp16(uint32_t d, const void* s) {
    asm volatile("cp.async.cg.shared.global [%0], [%1], 16;" :: "r"(d), "l"(s));
}
#define CP_COMMIT() asm volatile("cp.async.commit_group;" ::: "memory")
#define CP_WAIT1()  asm volatile("cp.async.wait_group 1;" ::: "memory")
#define CP_WAIT0()  asm volatile("cp.async.wait_group 0;" ::: "memory")

__device__ __forceinline__ void ldm_x4(uint32_t addr, uint32_t r[4]) {
    asm volatile("ldmatrix.sync.aligned.m8n8.x4.shared.b16 {%0,%1,%2,%3}, [%4];"
        : "=r"(r[0]), "=r"(r[1]), "=r"(r[2]), "=r"(r[3]) : "r"(addr));
}
__device__ __forceinline__ void ldm_x4t(uint32_t addr, uint32_t r[4]) {
    asm volatile("ldmatrix.sync.aligned.m8n8.x4.trans.shared.b16 {%0,%1,%2,%3}, [%4];"
        : "=r"(r[0]), "=r"(r[1]), "=r"(r[2]), "=r"(r[3]) : "r"(addr));
}
__device__ __forceinline__ void mma16816(float c[4], const uint32_t a[4],
                                         const uint32_t b[2]) {
    asm volatile(
        "mma.sync.aligned.m16n8k16.row.col.f32.bf16.bf16.f32 "
        "{%0,%1,%2,%3}, {%4,%5,%6,%7}, {%8,%9}, {%0,%1,%2,%3};"
        : "+f"(c[0]), "+f"(c[1]), "+f"(c[2]), "+f"(c[3])
        : "r"(a[0]), "r"(a[1]), "r"(a[2]), "r"(a[3]), "r"(b[0]), "r"(b[1]));
}

// ============================================================================
// split kernels (device-global targets referenced ONLY in device code)
// ============================================================================
__device__ __forceinline__ void split_store(float4 v, __nv_bfloat16* hi,
                                            __nv_bfloat16* lo, int i) {
    __nv_bfloat16 h0, h1, h2, h3, l0, l1, l2, l3;
    split2(v.x, h0, l0); split2(v.y, h1, l1);
    split2(v.z, h2, l2); split2(v.w, h3, l3);
    __nv_bfloat162 a, b, c, d;
    a.x = h0; a.y = h1; b.x = h2; b.y = h3;
    c.x = l0; c.y = l1; d.x = l2; d.y = l3;
    ((__nv_bfloat162*)hi)[2 * i]     = a;
    ((__nv_bfloat162*)hi)[2 * i + 1] = b;
    ((__nv_bfloat162*)lo)[2 * i]     = c;
    ((__nv_bfloat162*)lo)[2 * i + 1] = d;
}
__global__ void __launch_bounds__(256)
k_split_x(const float4* __restrict__ x) {
    int i = blockIdx.x * 256 + threadIdx.x;
    split_store(x[i], g_a_hi, g_a_lo, i);
}
__global__ void __launch_bounds__(256)
k_split_dst(const float4* __restrict__ src, __nv_bfloat16* __restrict__ hi,
            __nv_bfloat16* __restrict__ lo) {
    int i = blockIdx.x * 256 + threadIdx.x;
    split_store(src[i], hi, lo, i);
}
__global__ void __launch_bounds__(256)
k_split_w2(const float4* __restrict__ Wo) {
    int i = blockIdx.x * 256 + threadIdx.x;
    split_store(Wo[i], g_q_hi, g_q_lo, i);   // q planes dead after attention
}

// ============================================================================
// warp-MMA bf16x3 GEMM: all operands pre-split, pure cp.async fill,
// intra-CTA double buffering + 2 CTAs/SM.  CTA 128x64, BK=64, 8 warps.
// stage (55,296 B): [A_hi 18432][A_lo 18432][B_hi 9216][B_lo 9216]; x2.
// MODE 0: W = params (d_out scratch); scatter -> g_q/g_k/g_v planes (N=3072)
// MODE 1: W = g_q planes (W2 scratch);  write Cout fp32 + bias     (N=1024)
// ============================================================================
#define STAGE   55296
#define GEMM_SMEM (2 * STAGE)    // 110,592 B

__device__ __forceinline__ void gemm_issue(uint32_t st, int m0, int n0, int ko,
                                           const __nv_bfloat16* __restrict__ whi,
                                           const __nv_bfloat16* __restrict__ wlo,
                                           int N, int tid)
{
#pragma unroll
    for (int j = 0; j < 4; j++) {
        const int idx = tid + j * 256;      // 0..1023
        const int r = idx >> 3;
        const int c = idx & 7;
        const size_t go = (size_t)(m0 + r) * CEMB + ko + c * 8;
        const uint32_t so = (uint32_t)(r * 144 + c * 16);
        cp16(st + so, g_a_hi + go);
        cp16(st + 18432 + so, g_a_lo + go);
    }
#pragma unroll
    for (int j = 0; j < 2; j++) {
        const int idx = tid + j * 256;      // 0..511
        const int k = idx >> 3;
        const int c = idx & 7;
        const size_t go = (size_t)(ko + k) * N + n0 + c * 8;
        const uint32_t so = (uint32_t)(k * 144 + c * 16);
        cp16(st + 36864 + so, whi + go);
        cp16(st + 46080 + so, wlo + go);
    }
}

template <int MODE>
__global__ void __launch_bounds__(256, 2)
mma_gemm(const __nv_bfloat16* __restrict__ whi_p,
         const __nv_bfloat16* __restrict__ wlo_p,
         const float* __restrict__ bias, float* __restrict__ Cout, int N)
{
    extern __shared__ char smem[];
    const uint32_t sbase = smem_u32(smem);

    const int tid  = threadIdx.x;
    const int lane = tid & 31;
    const int wid  = tid >> 5;
    const int m0   = blockIdx.y * 128;
    const int n0   = blockIdx.x * 64;
    const int wm0  = (wid & 3) * 32;
    const int wn0  = (wid >> 2) * 32;

    const __nv_bfloat16* whi = (MODE == 0) ? whi_p : (const __nv_bfloat16*)g_q_hi;
    const __nv_bfloat16* wlo = (MODE == 0) ? wlo_p : (const __nv_bfloat16*)g_q_lo;

    float acc[2][4][4];
#pragma unroll
    for (int mt = 0; mt < 2; mt++)
#pragma unroll
        for (int nt = 0; nt < 4; nt++)
#pragma unroll
            for (int e = 0; e < 4; e++) acc[mt][nt][e] = 0.0f;

    const uint32_t a_off = (uint32_t)((wm0 + (lane & 15)) * 144 + (lane >> 4) * 16);
    const uint32_t b_off = (uint32_t)(36864 +
        (((lane >> 3) & 1) * 8 + (lane & 7)) * 144 + wn0 * 2 + (lane >> 4) * 16);

    gemm_issue(sbase, m0, n0, 0, whi, wlo, N, tid);
    CP_COMMIT();

    constexpr int NKT = CEMB / 64;   // 16
    for (int kt = 0; kt < NKT; kt++) {
        const uint32_t st = sbase + (uint32_t)(kt & 1) * STAGE;
        if (kt + 1 < NKT) {
            gemm_issue(sbase + (uint32_t)((kt + 1) & 1) * STAGE,
                       m0, n0, (kt + 1) * 64, whi, wlo, N, tid);
            CP_COMMIT();
            CP_WAIT1();
        } else {
            CP_WAIT0();
        }
        __syncthreads();

        const uint32_t aBase = st + a_off;
        const uint32_t bBase = st + b_off;
#pragma unroll
        for (int ks = 0; ks < 4; ks++) {
            uint32_t bhi[2][4], blo[2][4];
#pragma unroll
            for (int g = 0; g < 2; g++) {
                const uint32_t bd = bBase + (uint32_t)(ks * 16 * 144 + g * 32);
                ldm_x4t(bd, bhi[g]);
                ldm_x4t(bd + 9216, blo[g]);
            }
#pragma unroll
            for (int mt = 0; mt < 2; mt++) {
                uint32_t ahi[4], alo[4];
                const uint32_t ad = aBase + (uint32_t)(mt * 16 * 144 + ks * 32);
                ldm_x4(ad, ahi);
                ldm_x4(ad + 18432, alo);
#pragma unroll
                for (int g = 0; g < 2; g++)
#pragma unroll
                    for (int h2 = 0; h2 < 2; h2++) {
                        const int nt = g * 2 + h2;
                        mma16816(acc[mt][nt], ahi, &bhi[g][h2 * 2]);
                        mma16816(acc[mt][nt], alo, &bhi[g][h2 * 2]);
                        mma16816(acc[mt][nt], ahi, &blo[g][h2 * 2]);
                    }
            }
        }
        __syncthreads();   // stage reads done before it is re-issued
    }

    // ---------------- epilogue ----------------
#pragma unroll
    for (int mt = 0; mt < 2; mt++) {
        const int mrow = m0 + wm0 + mt * 16 + (lane >> 2);
#pragma unroll
        for (int nt = 0; nt < 4; nt++) {
            const int nb = n0 + wn0 + nt * 8 + (lane & 3) * 2;
            const float b0 = bias[nb], b1 = bias[nb + 1];
            const float* a = acc[mt][nt];
            if (MODE == 0) {
                const int hh = nb / 192;
                const int e  = nb - hh * 192;
                const int wh = e >> 6;
                const int d0 = e & 63;
                __nv_bfloat16* ah = (wh == 0) ? g_q_hi : (wh == 1) ? g_k_hi : g_v_hi;
                __nv_bfloat16* al = (wh == 0) ? g_q_lo : (wh == 1) ? g_k_lo : g_v_lo;
                const int bi = mrow >> 11;
                const int t  = mrow & (T_SEQ - 1);
                const size_t o0 = ((size_t)((bi * NH + hh) * T_SEQ + t)) * HS + d0;
                *(uint32_t*)(ah + o0) = pack_hi(a[0] + b0, a[1] + b1);
                *(uint32_t*)(al + o0) = pack_lo(a[0] + b0, a[1] + b1);
                const size_t o1 = o0 + (size_t)8 * HS;
                *(uint32_t*)(ah + o1) = pack_hi(a[2] + b0, a[3] + b1);
                *(uint32_t*)(al + o1) = pack_lo(a[2] + b0, a[3] + b1);
            } else {
                float* dst0 = Cout + (size_t)mrow * N + nb;
                *(float2*)dst0 = make_float2(a[0] + b0, a[1] + b1);
                float* dst1 = Cout + (size_t)(mrow + 8) * N + nb;
                *(float2*)dst1 = make_float2(a[2] + b0, a[3] + b1);
            }
        }
    }
}

// ============================================================================
// Causal flash attention (BYTE-IDENTICAL to passing round-11 kernel).
// mma.sync bf16x3, BKV=128, cp.async double-buffered K/V, (256,1).
// ============================================================================
#define KVBUF (4 * 18432)
#define ATTN_SMEM (2 * 18432 + 2 * KVBUF)   // 184,320 B

__device__ __forceinline__ void issue_kv(uint32_t kvb, size_t go_base, int tid) {
#pragma unroll
    for (int j = 0; j < 4; j++) {
        const int idx = tid + j * 256;
        const int r = idx >> 3;
        const int c = idx & 7;
        const size_t go = go_base + (size_t)r * HS + c * 8;
        const uint32_t so = (uint32_t)(r * 144 + c * 16);
        cp16(kvb + 0 * 18432 + so, g_k_hi + go);
        cp16(kvb + 1 * 18432 + so, g_k_lo + go);
        cp16(kvb + 2 * 18432 + so, g_v_hi + go);
        cp16(kvb + 3 * 18432 + so, g_v_lo + go);
    }
}

__global__ void __launch_bounds__(256, 1)
attn_mma(void)
{
    extern __shared__ char smem[];
    const uint32_t sbase = smem_u32(smem);
    const int tid  = threadIdx.x;
    const int lane = tid & 31;
    const int wid  = tid >> 5;

    const int qt = gridDim.x - 1 - blockIdx.x;
    const int h  = blockIdx.y;
    const int b  = blockIdx.z;
    const int q0 = qt * 128;

    const size_t base  = (size_t)(b * NH + h) * T_SEQ * HS;
    const size_t qbase = base + (size_t)q0 * HS;

#pragma unroll
    for (int j = 0; j < 4; j++) {
        const int idx = tid + j * 256;
        const int r = idx >> 3;
        const int c = idx & 7;
        const size_t go = qbase + (size_t)r * HS + c * 8;
        const uint32_t so = (uint32_t)(r * 144 + c * 16);
        cp16(sbase + so, g_q_hi + go);
        cp16(sbase + 18432 + so, g_q_lo + go);
    }
    issue_kv(sbase + 2 * 18432, base, tid);
    CP_COMMIT();

    const uint32_t a_off = (uint32_t)((wid * 16 + (lane & 15)) * 144 + (lane >> 4) * 16);
    const uint32_t k_off = (uint32_t)(((((lane >> 4) << 3) + (lane & 7)) * 144) +
                                      ((lane >> 3) & 1) * 16);
    const uint32_t v_off = (uint32_t)(((((lane >> 3) & 1) * 8 + (lane & 7)) * 144) +
                                      (lane >> 4) * 16);
    const uint32_t aBase = sbase + a_off;

    float o[8][4];
#pragma unroll
    for (int nt = 0; nt < 8; nt++)
#pragma unroll
        for (int e = 0; e < 4; e++) o[nt][e] = 0.0f;
    float m0 = -1e30f, m1 = -1e30f, l0 = 0.0f, l1 = 0.0f;

    const int rloc0 = wid * 16 + (lane >> 2);
    const int rloc1 = rloc0 + 8;

    for (int kt = 0; kt <= qt; kt++) {
        const uint32_t kvb = sbase + 2 * 18432 + (uint32_t)(kt & 1) * KVBUF;
        if (kt < qt) {
            issue_kv(sbase + 2 * 18432 + (uint32_t)((kt + 1) & 1) * KVBUF,
                     base + (size_t)(kt + 1) * 128 * HS, tid);
            CP_COMMIT();
            CP_WAIT1();
        } else {
            CP_WAIT0();
        }
        __syncthreads();

        const uint32_t kBase = kvb + k_off;
        const uint32_t vBase = kvb + 2 * 18432 + v_off;

        float s[16][4];
#pragma unroll
        for (int nt = 0; nt < 16; nt++)
#pragma unroll
            for (int e = 0; e < 4; e++) s[nt][e] = 0.0f;

#pragma unroll
        for (int ks = 0; ks < 4; ks++) {
            uint32_t ahi[4], alo[4];
            ldm_x4(aBase + ks * 32, ahi);
            ldm_x4(aBase + 18432 + ks * 32, alo);
#pragma unroll
            for (int g = 0; g < 8; g++) {
                uint32_t kh[4], kl[4];
                const uint32_t kd = kBase + (uint32_t)(g * 16 * 144 + ks * 32);
                ldm_x4(kd, kh);
                ldm_x4(kd + 18432, kl);
#pragma unroll
                for (int h2 = 0; h2 < 2; h2++) {
                    const int nt = g * 2 + h2;
                    mma16816(s[nt], ahi, &kh[h2 * 2]);
                    mma16816(s[nt], alo, &kh[h2 * 2]);
                    mma16816(s[nt], ahi, &kl[h2 * 2]);
                }
            }
        }

#pragma unroll
        for (int nt = 0; nt < 16; nt++)
#pragma unroll
            for (int e = 0; e < 4; e++) s[nt][e] *= 0.125f;

        if (kt == qt) {
#pragma unroll
            for (int nt = 0; nt < 16; nt++) {
                const int c0 = nt * 8 + (lane & 3) * 2;
                const int c1 = c0 + 1;
                if (c0 > rloc0) s[nt][0] = -1e30f;
                if (c1 > rloc0) s[nt][1] = -1e30f;
                if (c0 > rloc1) s[nt][2] = -1e30f;
                if (c1 > rloc1) s[nt][3] = -1e30f;
            }
        }

        float mx0 = -1e30f, mx1 = -1e30f;
#pragma unroll
        for (int nt = 0; nt < 16; nt++) {
            mx0 = fmaxf(mx0, fmaxf(s[nt][0], s[nt][1]));
            mx1 = fmaxf(mx1, fmaxf(s[nt][2], s[nt][3]));
        }
        mx0 = fmaxf(mx0, __shfl_xor_sync(0xffffffffu, mx0, 1));
        mx0 = fmaxf(mx0, __shfl_xor_sync(0xffffffffu, mx0, 2));
        mx1 = fmaxf(mx1, __shfl_xor_sync(0xffffffffu, mx1, 1));
        mx1 = fmaxf(mx1, __shfl_xor_sync(0xffffffffu, mx1, 2));

        const float mn0 = fmaxf(m0, mx0);
        const float mn1 = fmaxf(m1, mx1);
        const float sc0 = __expf(m0 - mn0);
        const float sc1 = __expf(m1 - mn1);
        m0 = mn0; m1 = mn1;

        float ls0 = 0.0f, ls1 = 0.0f;
#pragma unroll
        for (int nt = 0; nt < 16; nt++) {
            s[nt][0] = __expf(s[nt][0] - mn0);
            s[nt][1] = __expf(s[nt][1] - mn0);
            s[nt][2] = __expf(s[nt][2] - mn1);
            s[nt][3] = __expf(s[nt][3] - mn1);
            ls0 += s[nt][0] + s[nt][1];
            ls1 += s[nt][2] + s[nt][3];
        }
        ls0 += __shfl_xor_sync(0xffffffffu, ls0, 1);
        ls0 += __shfl_xor_sync(0xffffffffu, ls0, 2);
        ls1 += __shfl_xor_sync(0xffffffffu, ls1, 1);
        ls1 += __shfl_xor_sync(0xffffffffu, ls1, 2);
        l0 = l0 * sc0 + ls0;
        l1 = l1 * sc1 + ls1;

#pragma unroll
        for (int nt = 0; nt < 8; nt++) {
            o[nt][0] *= sc0; o[nt][1] *= sc0;
            o[nt][2] *= sc1; o[nt][3] *= sc1;
        }

#pragma unroll
        for (int ksv = 0; ksv < 8; ksv++) {
            const int nt0 = 2 * ksv, nt1 = 2 * ksv + 1;
            uint32_t ph[4], pl[4];
            ph[0] = pack_hi(s[nt0][0], s[nt0][1]);
            ph[1] = pack_hi(s[nt0][2], s[nt0][3]);
            ph[2] = pack_hi(s[nt1][0], s[nt1][1]);
            ph[3] = pack_hi(s[nt1][2], s[nt1][3]);
            pl[0] = pack_lo(s[nt0][0], s[nt0][1]);
            pl[1] = pack_lo(s[nt0][2], s[nt0][3]);
            pl[2] = pack_lo(s[nt1][0], s[nt1][1]);
            pl[3] = pack_lo(s[nt1][2], s[nt1][3]);
#pragma unroll
            for (int g = 0; g < 4; g++) {
                uint32_t vh[4], vl[4];
                const uint32_t vd = vBase + (uint32_t)(ksv * 16 * 144 + g * 32);
                ldm_x4t(vd, vh);
                ldm_x4t(vd + 18432, vl);
#pragma unroll
                for (int h2 = 0; h2 < 2; h2++) {
                    const int nt = g * 2 + h2;
                    mma16816(o[nt], ph, &vh[h2 * 2]);
                    mma16816(o[nt], pl, &vh[h2 * 2]);
                    mma16816(o[nt], ph, &vl[h2 * 2]);
                }
            }
        }
        __syncthreads();
    }

    const float inv0 = 1.0f / l0;
    const float inv1 = 1.0f / l1;
    const int grow0 = q0 + rloc0;
    const int grow1 = q0 + rloc1;
#pragma unroll
    for (int nt = 0; nt < 8; nt++) {
        const int d = nt * 8 + (lane & 3) * 2;
        const size_t o0 = ((size_t)(b * T_SEQ + grow0)) * CEMB + h * HS + d;
        *(uint32_t*)(g_a_hi + o0) = pack_hi(o[nt][0] * inv0, o[nt][1] * inv0);
        *(uint32_t*)(g_a_lo + o0) = pack_lo(o[nt][0] * inv0, o[nt][1] * inv0);
        const size_t o1 = ((size_t)(b * T_SEQ + grow1)) * CEMB + h * HS + d;
        *(uint32_t*)(g_a_hi + o1) = pack_hi(o[nt][2] * inv1, o[nt][3] * inv1);
        *(uint32_t*)(g_a_lo + o1) = pack_lo(o[nt][2] * inv1, o[nt][3] * inv1);
    }
}

// ============================================================================
// launch
// ============================================================================
extern "C" void kernel_launch(void* const* d_in, const int* in_sizes, int n_in,
                              void* d_out, int out_size)
{
    const float* x    = (const float*)d_in[0];
    const float* Wqkv = (const float*)d_in[1];
    const float* bqkv = (const float*)d_in[2];
    const float* Wo   = (const float*)d_in[3];
    const float* bo   = (const float*)d_in[4];
    float* out = (float*)d_out;

    // W1 planes live inside d_out (16 MiB): hi at 0, lo at +6 MiB.
    __nv_bfloat16* w1hi = (__nv_bfloat16*)d_out;
    __nv_bfloat16* w1lo = w1hi + (size_t)CEMB * C3;

    cudaFuncSetAttribute(attn_mma, cudaFuncAttributeMaxDynamicSharedMemorySize, ATTN_SMEM);
    cudaFuncSetAttribute(mma_gemm<0>, cudaFuncAttributeMaxDynamicSharedMemorySize, GEMM_SMEM);
    cudaFuncSetAttribute(mma_gemm<1>, cudaFuncAttributeMaxDynamicSharedMemorySize, GEMM_SMEM);

    // 0) splits: x -> g_a planes; W1 -> d_out scratch planes
    k_split_x  <<<(MTOT * CEMB / 4) / 256, 256>>>((const float4*)x);
    k_split_dst<<<(CEMB * C3 / 4) / 256, 256>>>((const float4*)Wqkv, w1hi, w1lo);

    // 1) QKV projection -> split g_q/g_k/g_v planes
    mma_gemm<0><<<dim3(C3 / 64, MTOT / 128), 256, GEMM_SMEM>>>(w1hi, w1lo,
                                                               bqkv, nullptr, C3);

    // 2) causal flash attention -> split g_a planes
    attn_mma<<<dim3(T_SEQ / 128, NH, NB), 256, ATTN_SMEM>>>();

    // 3) W2 split into g_q plane space (dead after attention)
    k_split_w2<<<(CEMB * CEMB / 4) / 256, 256>>>((const float4*)Wo);

    // 4) output projection -> d_out (overwrites W1 scratch completely)
    mma_gemm<1><<<dim3(CEMB / 64, MTOT / 128), 256, GEMM_SMEM>>>(nullptr, nullptr,
                                                                 bo, out, CEMB);
}